// round 2
// baseline (speedup 1.0000x reference)
#include <cuda_runtime.h>
#include <math.h>
#include <stdint.h>

// Problem constants (fixed by the dataset)
#define MAXN 100000
#define MAXE 1600000
#define MAXT (MAXN + MAXE)
#define BSZ  1024
#define CH   30
#define SEQL 20

// ---------------- scratch (static device globals; no allocation) -------------
__device__ float d_h[(size_t)MAXN * 128];   // GAT h
__device__ float d_g1[(size_t)MAXN * 128];  // GAT out g1
__device__ float d_h2[(size_t)MAXN * 64];   // h2 = g1@W2 ; later reused as agg2
__device__ float d_g2[(size_t)MAXN * 64];   // g2 (after GCN-64 + lrelu)
__device__ float d_as[MAXN * 4];
__device__ float d_ad[MAXN * 4];
__device__ int   d_deg[MAXN];
__device__ int   d_rowptr[MAXN + 1];
__device__ int   d_cursor[MAXN];
__device__ int   d_col[MAXT];
__device__ int   d_bsums[1024];
__device__ float d_dinv[MAXN];
__device__ float d_pool[BSZ * 128];
__device__ float d_cntb[BSZ];
__device__ float d_s1[BSZ * 64 * 18];
__device__ float d_s2[BSZ * 64 * 16];
__device__ float d_sfc[BSZ * 64];

__device__ __forceinline__ float lrelu(float x, float s) { return x >= 0.f ? x : s * x; }
__device__ __forceinline__ float warpMax(float v) {
#pragma unroll
    for (int o = 16; o > 0; o >>= 1) v = fmaxf(v, __shfl_xor_sync(0xffffffffu, v, o));
    return v;
}
__device__ __forceinline__ float warpSum(float v) {
#pragma unroll
    for (int o = 16; o > 0; o >>= 1) v += __shfl_xor_sync(0xffffffffu, v, o);
    return v;
}

// ---------------- K1: h = x @ W_gat ; a_s, a_d ------------------------------
__global__ void k_gat_node(const float* __restrict__ x, const float* __restrict__ Wg,
                           const float* __restrict__ asrc, const float* __restrict__ adst, int n) {
    int c = threadIdx.x;
    float w[9];
#pragma unroll
    for (int f = 0; f < 9; f++) w[f] = Wg[f * 128 + c];
    float atts = asrc[c], attd = adst[c];
    __shared__ float sx[16 * 9];
    int base = blockIdx.x * 16;
    int cnt = min(16, n - base);
    if (cnt <= 0) return;
    for (int i = threadIdx.x; i < cnt * 9; i += 128) sx[i] = x[base * 9 + i];
    __syncthreads();
    int wid = c >> 5;
    for (int t = 0; t < cnt; t++) {
        float h = 0.f;
#pragma unroll
        for (int f = 0; f < 9; f++) h += sx[t * 9 + f] * w[f];
        d_h[(size_t)(base + t) * 128 + c] = h;
        float vs = warpSum(h * atts);
        float vd = warpSum(h * attd);
        if ((c & 31) == 0) {
            d_as[(base + t) * 4 + wid] = vs;
            d_ad[(base + t) * 4 + wid] = vd;
        }
    }
}

// ---------------- CSR build --------------------------------------------------
__global__ void k_deg_init(int n) {
    int i = blockIdx.x * blockDim.x + threadIdx.x;
    if (i < n) d_deg[i] = 1;  // self loop
}
__global__ void k_count(const int* __restrict__ ei, int E) {
    for (int e = blockIdx.x * blockDim.x + threadIdx.x; e < E; e += gridDim.x * blockDim.x)
        atomicAdd(&d_deg[ei[E + e]], 1);
}
__global__ void k_scan1(int n) {
    __shared__ int ss[512];
    int idx = blockIdx.x * 512 + threadIdx.x;
    int val = (idx < n) ? d_deg[idx] : 0;
    ss[threadIdx.x] = val;
    __syncthreads();
#pragma unroll
    for (int off = 1; off < 512; off <<= 1) {
        int t = (threadIdx.x >= off) ? ss[threadIdx.x - off] : 0;
        __syncthreads();
        ss[threadIdx.x] += t;
        __syncthreads();
    }
    if (idx < n) d_rowptr[idx] = ss[threadIdx.x] - val;  // exclusive
    if (threadIdx.x == 511) d_bsums[blockIdx.x] = ss[511];
}
__global__ void k_scan2(int nb) {
    __shared__ int ss[512];
    int v = (threadIdx.x < nb) ? d_bsums[threadIdx.x] : 0;
    ss[threadIdx.x] = v;
    __syncthreads();
#pragma unroll
    for (int off = 1; off < 512; off <<= 1) {
        int t = (threadIdx.x >= off) ? ss[threadIdx.x - off] : 0;
        __syncthreads();
        ss[threadIdx.x] += t;
        __syncthreads();
    }
    if (threadIdx.x < nb) d_bsums[threadIdx.x] = ss[threadIdx.x] - v;  // exclusive
}
__global__ void k_scan3(int n, int tot) {
    int idx = blockIdx.x * 512 + threadIdx.x;
    if (idx < n) d_rowptr[idx] += d_bsums[blockIdx.x];
    if (idx == 0) d_rowptr[n] = tot;
}
__global__ void k_selfloop(int n) {
    int i = blockIdx.x * blockDim.x + threadIdx.x;
    if (i < n) {
        int p = d_rowptr[i];
        d_col[p] = i;
        d_cursor[i] = p + 1;
        d_dinv[i] = rsqrtf((float)d_deg[i]);
    }
}
__global__ void k_scatter(const int* __restrict__ ei, int E) {
    for (int e = blockIdx.x * blockDim.x + threadIdx.x; e < E; e += gridDim.x * blockDim.x) {
        int s = ei[e], d = ei[E + e];
        int pos = atomicAdd(&d_cursor[d], 1);
        d_col[pos] = s;
    }
}

// ---------------- GAT aggregate (one warp per dst node, online softmax) ------
__global__ void k_gat_agg(const float* __restrict__ bias, int n) {
    int warp = (blockIdx.x * blockDim.x + threadIdx.x) >> 5;
    int lane = threadIdx.x & 31;
    if (warp >= n) return;
    int i = warp;
    int start = d_rowptr[i], end = d_rowptr[i + 1];
    float4 ad4 = *(const float4*)(d_ad + 4 * i);
    float m0 = -1e30f, m1 = -1e30f, m2 = -1e30f, m3 = -1e30f;
    float s0 = 0.f, s1 = 0.f, s2 = 0.f, s3 = 0.f;
    for (int j = start + lane; j < end; j += 32) {
        int s = d_col[j];
        float4 a = *(const float4*)(d_as + 4 * s);
        float e0 = lrelu(a.x + ad4.x, 0.2f);
        float e1 = lrelu(a.y + ad4.y, 0.2f);
        float e2 = lrelu(a.z + ad4.z, 0.2f);
        float e3 = lrelu(a.w + ad4.w, 0.2f);
        if (e0 <= m0) s0 += expf(e0 - m0); else { s0 = s0 * expf(m0 - e0) + 1.f; m0 = e0; }
        if (e1 <= m1) s1 += expf(e1 - m1); else { s1 = s1 * expf(m1 - e1) + 1.f; m1 = e1; }
        if (e2 <= m2) s2 += expf(e2 - m2); else { s2 = s2 * expf(m2 - e2) + 1.f; m2 = e2; }
        if (e3 <= m3) s3 += expf(e3 - m3); else { s3 = s3 * expf(m3 - e3) + 1.f; m3 = e3; }
    }
    float M0 = warpMax(m0), M1 = warpMax(m1), M2 = warpMax(m2), M3 = warpMax(m3);
    s0 = warpSum(s0 * expf(m0 - M0));
    s1 = warpSum(s1 * expf(m1 - M1));
    s2 = warpSum(s2 * expf(m2 - M2));
    s3 = warpSum(s3 * expf(m3 - M3));
    float i0 = 1.f / (s0 + 1e-16f), i1 = 1.f / (s1 + 1e-16f);
    float i2 = 1.f / (s2 + 1e-16f), i3 = 1.f / (s3 + 1e-16f);
    int hh = lane >> 3;  // head of this lane's 4 channels
    float mm = hh < 2 ? (hh == 0 ? M0 : M1) : (hh == 2 ? M2 : M3);
    float ii = hh < 2 ? (hh == 0 ? i0 : i1) : (hh == 2 ? i2 : i3);
    float aad = hh < 2 ? (hh == 0 ? ad4.x : ad4.y) : (hh == 2 ? ad4.z : ad4.w);
    float4 acc = make_float4(0.f, 0.f, 0.f, 0.f);
    for (int j = start; j < end; j++) {
        int s = d_col[j];
        float4 a = *(const float4*)(d_as + 4 * s);
        float av = hh < 2 ? (hh == 0 ? a.x : a.y) : (hh == 2 ? a.z : a.w);
        float alpha = expf(lrelu(av + aad, 0.2f) - mm) * ii;
        const float4 hv = *(const float4*)(d_h + (size_t)s * 128 + 4 * lane);
        acc.x += alpha * hv.x; acc.y += alpha * hv.y;
        acc.z += alpha * hv.z; acc.w += alpha * hv.w;
    }
    float4 b4 = *(const float4*)(bias + 4 * lane);
    float4 o;
    o.x = lrelu(acc.x + b4.x, 0.01f);
    o.y = lrelu(acc.y + b4.y, 0.01f);
    o.z = lrelu(acc.z + b4.z, 0.01f);
    o.w = lrelu(acc.w + b4.w, 0.01f);
    *(float4*)(d_g1 + (size_t)i * 128 + 4 * lane) = o;
}

// ---------------- h2 = g1[N,128] @ W2[128,64] --------------------------------
__global__ void k_mm1(const float* __restrict__ W, int n) {
    __shared__ float sW[128 * 64];
    __shared__ float sX[4 * 128];
    for (int i = threadIdx.x; i < 128 * 64; i += 256) sW[i] = W[i];
    for (int base = blockIdx.x * 4; base < n; base += gridDim.x * 4) {
        __syncthreads();
        int cnt = min(4, n - base);
        for (int i = threadIdx.x; i < cnt * 128; i += 256) sX[i] = d_g1[(size_t)base * 128 + i];
        __syncthreads();
        int ln = threadIdx.x >> 6, c = threadIdx.x & 63;
        if (ln < cnt) {
            float acc = 0.f;
#pragma unroll 16
            for (int k = 0; k < 128; k++) acc += sX[ln * 128 + k] * sW[k * 64 + c];
            d_h2[(size_t)(base + ln) * 64 + c] = acc;
        }
    }
}

// ---------------- 64-dim GCN aggregation (warp per dst node) -----------------
// out[i] = sum_j dinv[s]*dinv[i] * in[s]  (+ optional bias + lrelu)
__device__ __forceinline__ void agg64_body(const float* __restrict__ in, float* __restrict__ outp,
                                           const float* __restrict__ bias, int n, bool act) {
    int warp = (blockIdx.x * blockDim.x + threadIdx.x) >> 5;
    int lane = threadIdx.x & 31;
    if (warp >= n) return;
    int i = warp;
    int start = d_rowptr[i], end = d_rowptr[i + 1];
    float dvi = d_dinv[i];
    float ax = 0.f, ay = 0.f;
    for (int j = start; j < end; j++) {
        int s = d_col[j];
        float w = d_dinv[s] * dvi;
        float2 v = *(const float2*)(in + (size_t)s * 64 + 2 * lane);
        ax += w * v.x; ay += w * v.y;
    }
    float2 o;
    if (act) {
        float2 b2 = *(const float2*)(bias + 2 * lane);
        o.x = lrelu(ax + b2.x, 0.01f);
        o.y = lrelu(ay + b2.y, 0.01f);
    } else {
        o.x = ax; o.y = ay;
    }
    *(float2*)(outp + (size_t)i * 64 + 2 * lane) = o;
}
__global__ void k_agg64_act(const float* __restrict__ bias, int n) {
    agg64_body(d_h2, d_g2, bias, n, true);     // g2 = lrelu(A@h2 + b2)
}
__global__ void k_agg64_plain(int n) {
    agg64_body(d_g2, d_h2, nullptr, n, false); // agg2 = A@g2 (reuse d_h2)
}

// ---------------- layer-3 matmul (64->128) + bias + lrelu + pool -------------
__global__ void k_mm3pool(const float* __restrict__ W, const float* __restrict__ bias,
                          const int* __restrict__ batch, int n) {
    __shared__ float sW[64 * 128];
    __shared__ float sb[128];
    __shared__ float sX[2 * 64];
    for (int i = threadIdx.x; i < 64 * 128; i += 256) sW[i] = W[i];
    if (threadIdx.x < 128) sb[threadIdx.x] = bias[threadIdx.x];
    for (int base = blockIdx.x * 2; base < n; base += gridDim.x * 2) {
        __syncthreads();
        int cnt = min(2, n - base);
        for (int i = threadIdx.x; i < cnt * 64; i += 256) sX[i] = d_h2[(size_t)base * 64 + i];
        __syncthreads();
        int ln = threadIdx.x >> 7, c = threadIdx.x & 127;
        if (ln < cnt) {
            float acc = 0.f;
#pragma unroll 16
            for (int k = 0; k < 64; k++) acc += sX[ln * 64 + k] * sW[k * 128 + c];
            float v = lrelu(acc + sb[c], 0.01f);
            atomicAdd(&d_pool[batch[base + ln] * 128 + c], v);
        }
    }
}

// ---------------- global mean pool helpers -----------------------------------
__global__ void k_zero_pool(int b) {
    int i = blockIdx.x * blockDim.x + threadIdx.x;
    if (i < b * 128) d_pool[i] = 0.f;
    if (i < b) d_cntb[i] = 0.f;
}
__global__ void k_cntb(const int* __restrict__ batch, int n) {
    int i = blockIdx.x * blockDim.x + threadIdx.x;
    if (i < n) atomicAdd(&d_cntb[batch[i]], 1.f);
}
__global__ void k_pool_div(int b) {
    int i = blockIdx.x * blockDim.x + threadIdx.x;
    if (i < b * 128) d_pool[i] /= fmaxf(d_cntb[i >> 7], 1.f);
}

// ---------------- sequence branch -------------------------------------------
__global__ void k_conv1(const float* __restrict__ seq, const float* __restrict__ w,
                        const float* __restrict__ bconv,
                        const float* __restrict__ g, const float* __restrict__ be,
                        const float* __restrict__ m, const float* __restrict__ v, int b) {
    __shared__ float sw[64 * 30 * 3];
    for (int i = threadIdx.x; i < 64 * 30 * 3; i += 256) sw[i] = w[i];
    __syncthreads();
    int total = b * 64 * 18;
    for (int idx = blockIdx.x * blockDim.x + threadIdx.x; idx < total; idx += gridDim.x * blockDim.x) {
        int pos = idx % 18, co = (idx / 18) % 64, bb = idx / (18 * 64);
        float acc = bconv[co];
        const float* xb = seq + bb * (CH * SEQL);
        const float* wp = sw + co * 90;
#pragma unroll
        for (int cin = 0; cin < 30; cin++) {
            const float* xp = xb + cin * 20 + pos;
            acc += xp[0] * wp[cin * 3 + 0] + xp[1] * wp[cin * 3 + 1] + xp[2] * wp[cin * 3 + 2];
        }
        float sc = g[co] * rsqrtf(v[co] + 1e-5f);
        float sh = be[co] - m[co] * sc;
        d_s1[idx] = lrelu(acc * sc + sh, 0.01f);
    }
}
__global__ void k_conv2(const float* __restrict__ w, const float* __restrict__ bconv,
                        const float* __restrict__ g, const float* __restrict__ be,
                        const float* __restrict__ m, const float* __restrict__ v, int b) {
    __shared__ float sw[64 * 64 * 3];  // 48KB
    for (int i = threadIdx.x; i < 64 * 64 * 3; i += 256) sw[i] = w[i];
    __syncthreads();
    int total = b * 64 * 16;
    for (int idx = blockIdx.x * blockDim.x + threadIdx.x; idx < total; idx += gridDim.x * blockDim.x) {
        int pos = idx % 16, co = (idx / 16) % 64, bb = idx / (16 * 64);
        float acc = bconv[co];
        const float* xb = d_s1 + bb * (64 * 18);
        const float* wp = sw + co * 192;
#pragma unroll 8
        for (int cin = 0; cin < 64; cin++) {
            const float* xp = xb + cin * 18 + pos;
            acc += xp[0] * wp[cin * 3 + 0] + xp[1] * wp[cin * 3 + 1] + xp[2] * wp[cin * 3 + 2];
        }
        float sc = g[co] * rsqrtf(v[co] + 1e-5f);
        float sh = be[co] - m[co] * sc;
        d_s2[idx] = lrelu(acc * sc + sh, 0.01f);
    }
}

// fc1 as a tiled GEMM: [B,1024] @ [1024,64]  (64 rows per block)
__global__ void k_fc1g(const float* __restrict__ W, const float* __restrict__ bias, int b) {
    __shared__ float sX[64][65];
    __shared__ float sW[64][64];
    int c = threadIdx.x & 63, rg = threadIdx.x >> 6;  // rg in [0,4)
    int rowbase = blockIdx.x * 64;
    float acc[16];
#pragma unroll
    for (int r = 0; r < 16; r++) acc[r] = 0.f;
    for (int kt = 0; kt < 16; kt++) {
        __syncthreads();
        for (int i = threadIdx.x; i < 64 * 64; i += 256) {
            int r = i >> 6, k = i & 63;
            int row = rowbase + r;
            sX[r][k] = (row < b) ? d_s2[row * 1024 + kt * 64 + k] : 0.f;
        }
        for (int i = threadIdx.x; i < 64 * 64; i += 256) {
            int k = i >> 6, cc = i & 63;
            sW[k][cc] = W[(kt * 64 + k) * 64 + cc];
        }
        __syncthreads();
#pragma unroll
        for (int k = 0; k < 64; k++) {
            float w = sW[k][c];
#pragma unroll
            for (int r = 0; r < 16; r++) acc[r] += sX[rg * 16 + r][k] * w;
        }
    }
    float bb = bias[c];
#pragma unroll
    for (int r = 0; r < 16; r++) {
        int row = rowbase + rg * 16 + r;
        if (row < b) d_sfc[row * 64 + c] = acc[r] + bb;
    }
}

// ---------------- fusion + classifier ----------------------------------------
__global__ void k_head(const float* __restrict__ fusW, const float* __restrict__ fusb,
                       const float* __restrict__ c1W, const float* __restrict__ c1b,
                       const float* __restrict__ c3W, const float* __restrict__ c3b,
                       float* __restrict__ out) {
    __shared__ float comb[192];
    __shared__ float t1[128];
    __shared__ float red[2];
    int b = blockIdx.x, tid = threadIdx.x;
    comb[tid] = d_pool[b * 128 + tid];
    if (tid < 64) comb[128 + tid] = d_sfc[b * 64 + tid];
    __syncthreads();
    float a = fusb[tid];
    for (int k = 0; k < 192; k++) a += comb[k] * fusW[k * 128 + tid];
    t1[tid] = lrelu(a, 0.01f);
    __syncthreads();
    float vred = 0.f;
    if (tid < 64) {
        float acc = c1b[tid];
        for (int k = 0; k < 128; k++) acc += t1[k] * c1W[k * 64 + tid];
        vred = lrelu(acc, 0.01f) * c3W[tid];
    }
    vred = warpSum(vred);
    if ((tid & 31) == 0 && tid < 64) red[tid >> 5] = vred;
    __syncthreads();
    if (tid == 0) out[b] = red[0] + red[1] + c3b[0];
}

// ---------------- persistent side stream + events (host objects only) --------
static cudaStream_t get_side_stream() {
    static cudaStream_t s = nullptr;
    if (!s) cudaStreamCreateWithFlags(&s, cudaStreamNonBlocking);
    return s;
}
static cudaEvent_t get_event(int which) {
    static cudaEvent_t ev[2] = {nullptr, nullptr};
    if (!ev[which]) cudaEventCreateWithFlags(&ev[which], cudaEventDisableTiming);
    return ev[which];
}

// ---------------- launch ------------------------------------------------------
extern "C" void kernel_launch(void* const* d_in, const int* in_sizes, int n_in,
                              void* d_out, int out_size) {
    const float* x      = (const float*)d_in[0];
    const int*   ei     = (const int*)d_in[1];
    const int*   batch  = (const int*)d_in[2];
    const float* seq    = (const float*)d_in[3];
    const float* W_gat  = (const float*)d_in[4];
    const float* att_s  = (const float*)d_in[5];
    const float* att_d  = (const float*)d_in[6];
    const float* b_gat  = (const float*)d_in[7];
    const float* W2     = (const float*)d_in[8];
    const float* b2     = (const float*)d_in[9];
    const float* W3     = (const float*)d_in[10];
    const float* b3     = (const float*)d_in[11];
    const float* c1w    = (const float*)d_in[12];
    const float* c1b    = (const float*)d_in[13];
    const float* c2w    = (const float*)d_in[14];
    const float* c2b    = (const float*)d_in[15];
    const float* bn1g   = (const float*)d_in[16];
    const float* bn1b   = (const float*)d_in[17];
    const float* bn1m   = (const float*)d_in[18];
    const float* bn1v   = (const float*)d_in[19];
    const float* bn2g   = (const float*)d_in[20];
    const float* bn2b   = (const float*)d_in[21];
    const float* bn2m   = (const float*)d_in[22];
    const float* bn2v   = (const float*)d_in[23];
    const float* fc1W   = (const float*)d_in[24];
    const float* fc1b   = (const float*)d_in[25];
    const float* fusW   = (const float*)d_in[26];
    const float* fusb   = (const float*)d_in[27];
    const float* cl1W   = (const float*)d_in[28];
    const float* cl1b   = (const float*)d_in[29];
    const float* cl3W   = (const float*)d_in[30];
    const float* cl3b   = (const float*)d_in[31];
    float* out = (float*)d_out;

    int n = in_sizes[0] / 9;
    int E = in_sizes[1] / 2;
    int b = in_sizes[3] / (CH * SEQL);
    if (n > MAXN || E > MAXE || b > BSZ) return;

    cudaStream_t s1 = get_side_stream();
    cudaEvent_t evFork = get_event(0), evJoin = get_event(1);

    // --------- fork: side stream runs work independent of the CSR build -----
    cudaEventRecord(evFork, 0);
    cudaStreamWaitEvent(s1, evFork, 0);

    // side stream: sequence branch + GAT node transform + pool init
    k_conv1<<<512, 256, 0, s1>>>(seq, c1w, c1b, bn1g, bn1b, bn1m, bn1v, b);
    k_conv2<<<512, 256, 0, s1>>>(c2w, c2b, bn2g, bn2b, bn2m, bn2v, b);
    k_fc1g<<<(b + 63) / 64, 256, 0, s1>>>(fc1W, fc1b, b);
    k_gat_node<<<(n + 15) / 16, 128, 0, s1>>>(x, W_gat, att_s, att_d, n);
    k_zero_pool<<<(b * 128 + 255) / 256, 256, 0, s1>>>(b);
    k_cntb<<<(n + 255) / 256, 256, 0, s1>>>(batch, n);
    cudaEventRecord(evJoin, s1);

    // main stream: CSR build (degrees, scan, self loops, scatter)
    k_deg_init<<<(n + 255) / 256, 256>>>(n);
    k_count<<<2048, 256>>>(ei, E);
    int NB = (n + 511) / 512;
    k_scan1<<<NB, 512>>>(n);
    k_scan2<<<1, 512>>>(NB);
    k_scan3<<<NB, 512>>>(n, E + n);
    k_selfloop<<<(n + 255) / 256, 256>>>(n);
    k_scatter<<<2048, 256>>>(ei, E);

    // --------- join ----------------------------------------------------------
    cudaStreamWaitEvent(0, evJoin, 0);

    // GAT aggregate -> g1
    k_gat_agg<<<(n + 7) / 8, 256>>>(b_gat, n);

    // GCN layer 2: h2 = g1@W2 ; g2 = lrelu(A@h2 + b2)
    k_mm1<<<2048, 256>>>(W2, n);
    k_agg64_act<<<(n + 7) / 8, 256>>>(b2, n);

    // GCN layer 3 (linearity): agg2 = A@g2 (64-dim), then
    // per-node out = lrelu(agg2@W3 + b3) accumulated straight into the pool
    k_agg64_plain<<<(n + 7) / 8, 256>>>(n);
    k_mm3pool<<<1024, 256>>>(W3, b3, batch, n);
    k_pool_div<<<(b * 128 + 255) / 256, 256>>>(b);

    // fusion + classifier
    k_head<<<b, 128>>>(fusW, fusb, cl1W, cl1b, cl3W, cl3b, out);
}

// round 4
// speedup vs baseline: 1.2457x; 1.2457x over previous
#include <cuda_runtime.h>
#include <math.h>
#include <stdint.h>

// Problem constants (fixed by the dataset)
#define MAXN 100000
#define MAXE 1600000
#define MAXT (MAXN + MAXE)
#define BSZ  1024
#define CH   30
#define SEQL 20

// ---------------- scratch (static device globals; no allocation) -------------
__device__ float d_h[(size_t)MAXN * 128];   // GAT h
__device__ float d_g1[(size_t)MAXN * 128];  // GAT out g1
__device__ float d_h2[(size_t)MAXN * 64];   // h2 = g1@W2 ; later reused as agg2
__device__ float d_g2[(size_t)MAXN * 64];   // g2 (after GCN-64 + lrelu)
__device__ float d_as[MAXN * 4];
__device__ float d_ad[MAXN * 4];
__device__ int   d_deg[MAXN];
__device__ int   d_rowptr[MAXN + 1];
__device__ int   d_cursor[MAXN];
__device__ int   d_col[MAXT];
__device__ int   d_bsums[1024];
__device__ float d_dinv[MAXN];
__device__ float d_pool[BSZ * 128];
__device__ float d_cntb[BSZ];
__device__ float d_s1[BSZ * 64 * 18];
__device__ float d_s2[BSZ * 64 * 16];
__device__ float d_sfc[BSZ * 64];

__device__ __forceinline__ float lrelu(float x, float s) { return x >= 0.f ? x : s * x; }
__device__ __forceinline__ float warpMax(float v) {
#pragma unroll
    for (int o = 16; o > 0; o >>= 1) v = fmaxf(v, __shfl_xor_sync(0xffffffffu, v, o));
    return v;
}
__device__ __forceinline__ float warpSum(float v) {
#pragma unroll
    for (int o = 16; o > 0; o >>= 1) v += __shfl_xor_sync(0xffffffffu, v, o);
    return v;
}

// ---------------- K1: h = x @ W_gat ; a_s, a_d ------------------------------
__global__ void k_gat_node(const float* __restrict__ x, const float* __restrict__ Wg,
                           const float* __restrict__ asrc, const float* __restrict__ adst, int n) {
    int c = threadIdx.x;
    float w[9];
#pragma unroll
    for (int f = 0; f < 9; f++) w[f] = Wg[f * 128 + c];
    float atts = asrc[c], attd = adst[c];
    __shared__ float sx[16 * 9];
    int base = blockIdx.x * 16;
    int cnt = min(16, n - base);
    if (cnt <= 0) return;
    for (int i = threadIdx.x; i < cnt * 9; i += 128) sx[i] = x[base * 9 + i];
    __syncthreads();
    int wid = c >> 5;
    for (int t = 0; t < cnt; t++) {
        float h = 0.f;
#pragma unroll
        for (int f = 0; f < 9; f++) h += sx[t * 9 + f] * w[f];
        d_h[(size_t)(base + t) * 128 + c] = h;
        float vs = warpSum(h * atts);
        float vd = warpSum(h * attd);
        if ((c & 31) == 0) {
            d_as[(base + t) * 4 + wid] = vs;
            d_ad[(base + t) * 4 + wid] = vd;
        }
    }
}

// ---------------- CSR build --------------------------------------------------
__global__ void k_deg_init(int n) {
    int i = blockIdx.x * blockDim.x + threadIdx.x;
    if (i < n) d_deg[i] = 1;  // self loop
}
__global__ void k_count(const int* __restrict__ ei, int E) {
    for (int e = blockIdx.x * blockDim.x + threadIdx.x; e < E; e += gridDim.x * blockDim.x)
        atomicAdd(&d_deg[ei[E + e]], 1);
}
__global__ void k_scan1(int n) {
    __shared__ int ss[512];
    int idx = blockIdx.x * 512 + threadIdx.x;
    int val = (idx < n) ? d_deg[idx] : 0;
    ss[threadIdx.x] = val;
    __syncthreads();
#pragma unroll
    for (int off = 1; off < 512; off <<= 1) {
        int t = (threadIdx.x >= off) ? ss[threadIdx.x - off] : 0;
        __syncthreads();
        ss[threadIdx.x] += t;
        __syncthreads();
    }
    if (idx < n) d_rowptr[idx] = ss[threadIdx.x] - val;  // exclusive
    if (threadIdx.x == 511) d_bsums[blockIdx.x] = ss[511];
}
__global__ void k_scan2(int nb) {
    __shared__ int ss[512];
    int v = (threadIdx.x < nb) ? d_bsums[threadIdx.x] : 0;
    ss[threadIdx.x] = v;
    __syncthreads();
#pragma unroll
    for (int off = 1; off < 512; off <<= 1) {
        int t = (threadIdx.x >= off) ? ss[threadIdx.x - off] : 0;
        __syncthreads();
        ss[threadIdx.x] += t;
        __syncthreads();
    }
    if (threadIdx.x < nb) d_bsums[threadIdx.x] = ss[threadIdx.x] - v;  // exclusive
}
__global__ void k_scan3(int n, int tot) {
    int idx = blockIdx.x * 512 + threadIdx.x;
    if (idx < n) d_rowptr[idx] += d_bsums[blockIdx.x];
    if (idx == 0) d_rowptr[n] = tot;
}
__global__ void k_selfloop(int n) {
    int i = blockIdx.x * blockDim.x + threadIdx.x;
    if (i < n) {
        int p = d_rowptr[i];
        d_col[p] = i;
        d_cursor[i] = p + 1;
        d_dinv[i] = rsqrtf((float)d_deg[i]);
    }
}
__global__ void k_scatter(const int* __restrict__ ei, int E) {
    for (int e = blockIdx.x * blockDim.x + threadIdx.x; e < E; e += gridDim.x * blockDim.x) {
        int s = ei[e], d = ei[E + e];
        int pos = atomicAdd(&d_cursor[d], 1);
        d_col[pos] = s;
    }
}

// ---------------- GAT aggregate (one warp per dst node, online softmax) ------
__global__ void k_gat_agg(const float* __restrict__ bias, int n) {
    int warp = (blockIdx.x * blockDim.x + threadIdx.x) >> 5;
    int lane = threadIdx.x & 31;
    if (warp >= n) return;
    int i = warp;
    int start = d_rowptr[i], end = d_rowptr[i + 1];
    float4 ad4 = *(const float4*)(d_ad + 4 * i);
    float m0 = -1e30f, m1 = -1e30f, m2 = -1e30f, m3 = -1e30f;
    float s0 = 0.f, s1 = 0.f, s2 = 0.f, s3 = 0.f;
    for (int j = start + lane; j < end; j += 32) {
        int s = d_col[j];
        float4 a = *(const float4*)(d_as + 4 * s);
        float e0 = lrelu(a.x + ad4.x, 0.2f);
        float e1 = lrelu(a.y + ad4.y, 0.2f);
        float e2 = lrelu(a.z + ad4.z, 0.2f);
        float e3 = lrelu(a.w + ad4.w, 0.2f);
        if (e0 <= m0) s0 += expf(e0 - m0); else { s0 = s0 * expf(m0 - e0) + 1.f; m0 = e0; }
        if (e1 <= m1) s1 += expf(e1 - m1); else { s1 = s1 * expf(m1 - e1) + 1.f; m1 = e1; }
        if (e2 <= m2) s2 += expf(e2 - m2); else { s2 = s2 * expf(m2 - e2) + 1.f; m2 = e2; }
        if (e3 <= m3) s3 += expf(e3 - m3); else { s3 = s3 * expf(m3 - e3) + 1.f; m3 = e3; }
    }
    float M0 = warpMax(m0), M1 = warpMax(m1), M2 = warpMax(m2), M3 = warpMax(m3);
    s0 = warpSum(s0 * expf(m0 - M0));
    s1 = warpSum(s1 * expf(m1 - M1));
    s2 = warpSum(s2 * expf(m2 - M2));
    s3 = warpSum(s3 * expf(m3 - M3));
    float i0 = 1.f / (s0 + 1e-16f), i1 = 1.f / (s1 + 1e-16f);
    float i2 = 1.f / (s2 + 1e-16f), i3 = 1.f / (s3 + 1e-16f);
    int hh = lane >> 3;  // head of this lane's 4 channels
    float mm = hh < 2 ? (hh == 0 ? M0 : M1) : (hh == 2 ? M2 : M3);
    float ii = hh < 2 ? (hh == 0 ? i0 : i1) : (hh == 2 ? i2 : i3);
    float aad = hh < 2 ? (hh == 0 ? ad4.x : ad4.y) : (hh == 2 ? ad4.z : ad4.w);
    float4 acc = make_float4(0.f, 0.f, 0.f, 0.f);
    int j = start;
    // unroll-by-4: independent col loads up front -> MLP 4 on the h gathers
    for (; j + 4 <= end; j += 4) {
        int sA = d_col[j], sB = d_col[j + 1], sC = d_col[j + 2], sD = d_col[j + 3];
        float4 aA = *(const float4*)(d_as + 4 * sA);
        float4 aB = *(const float4*)(d_as + 4 * sB);
        float4 aC = *(const float4*)(d_as + 4 * sC);
        float4 aD = *(const float4*)(d_as + 4 * sD);
        const float4 hA = *(const float4*)(d_h + (size_t)sA * 128 + 4 * lane);
        const float4 hB = *(const float4*)(d_h + (size_t)sB * 128 + 4 * lane);
        const float4 hC = *(const float4*)(d_h + (size_t)sC * 128 + 4 * lane);
        const float4 hD = *(const float4*)(d_h + (size_t)sD * 128 + 4 * lane);
        float avA = hh < 2 ? (hh == 0 ? aA.x : aA.y) : (hh == 2 ? aA.z : aA.w);
        float avB = hh < 2 ? (hh == 0 ? aB.x : aB.y) : (hh == 2 ? aB.z : aB.w);
        float avC = hh < 2 ? (hh == 0 ? aC.x : aC.y) : (hh == 2 ? aC.z : aC.w);
        float avD = hh < 2 ? (hh == 0 ? aD.x : aD.y) : (hh == 2 ? aD.z : aD.w);
        float alA = expf(lrelu(avA + aad, 0.2f) - mm) * ii;
        float alB = expf(lrelu(avB + aad, 0.2f) - mm) * ii;
        float alC = expf(lrelu(avC + aad, 0.2f) - mm) * ii;
        float alD = expf(lrelu(avD + aad, 0.2f) - mm) * ii;
        acc.x += alA * hA.x + alB * hB.x + alC * hC.x + alD * hD.x;
        acc.y += alA * hA.y + alB * hB.y + alC * hC.y + alD * hD.y;
        acc.z += alA * hA.z + alB * hB.z + alC * hC.z + alD * hD.z;
        acc.w += alA * hA.w + alB * hB.w + alC * hC.w + alD * hD.w;
    }
    for (; j < end; j++) {
        int s = d_col[j];
        float4 a = *(const float4*)(d_as + 4 * s);
        float av = hh < 2 ? (hh == 0 ? a.x : a.y) : (hh == 2 ? a.z : a.w);
        float alpha = expf(lrelu(av + aad, 0.2f) - mm) * ii;
        const float4 hv = *(const float4*)(d_h + (size_t)s * 128 + 4 * lane);
        acc.x += alpha * hv.x; acc.y += alpha * hv.y;
        acc.z += alpha * hv.z; acc.w += alpha * hv.w;
    }
    float4 b4 = *(const float4*)(bias + 4 * lane);
    float4 o;
    o.x = lrelu(acc.x + b4.x, 0.01f);
    o.y = lrelu(acc.y + b4.y, 0.01f);
    o.z = lrelu(acc.z + b4.z, 0.01f);
    o.w = lrelu(acc.w + b4.w, 0.01f);
    *(float4*)(d_g1 + (size_t)i * 128 + 4 * lane) = o;
}

// ---------------- h2 = g1[N,128] @ W2[128,64]  (register-tiled) --------------
// block 256: 64 nodes/iter; thread = (cg 0..15 cols x4, ng 0..15 nodes x4)
__global__ void k_mm1(const float* __restrict__ W, int n) {
    __shared__ float sW[128 * 64];
    __shared__ float sX[64 * 128];
    const float4* W4 = (const float4*)W;
    float4* sW4 = (float4*)sW;
    for (int i = threadIdx.x; i < 128 * 64 / 4; i += 256) sW4[i] = W4[i];
    int cg = threadIdx.x & 15, ng = threadIdx.x >> 4;
    for (int base = blockIdx.x * 64; base < n; base += gridDim.x * 64) {
        __syncthreads();
        int cnt = min(64, n - base);
        {
            const float4* src = (const float4*)(d_g1 + (size_t)base * 128);
            float4* dst = (float4*)sX;
            int tot = cnt * 32;
            for (int i = threadIdx.x; i < tot; i += 256) dst[i] = src[i];
        }
        __syncthreads();
        float acc[4][4];
#pragma unroll
        for (int i = 0; i < 4; i++)
#pragma unroll
            for (int q = 0; q < 4; q++) acc[i][q] = 0.f;
        const float4* sWc = (const float4*)sW;
#pragma unroll 4
        for (int k = 0; k < 128; k++) {
            float4 w4 = sWc[k * 16 + cg];
#pragma unroll
            for (int i = 0; i < 4; i++) {
                float xv = sX[(ng * 4 + i) * 128 + k];
                acc[i][0] += xv * w4.x; acc[i][1] += xv * w4.y;
                acc[i][2] += xv * w4.z; acc[i][3] += xv * w4.w;
            }
        }
#pragma unroll
        for (int i = 0; i < 4; i++) {
            int node = base + ng * 4 + i;
            if (node < n) {
                float4 o = make_float4(acc[i][0], acc[i][1], acc[i][2], acc[i][3]);
                *(float4*)(d_h2 + (size_t)node * 64 + cg * 4) = o;
            }
        }
    }
}

// ---------------- 64-dim GCN aggregation (warp per dst, unroll 4) ------------
__device__ __forceinline__ void agg64_body(const float* __restrict__ in, float* __restrict__ outp,
                                           const float* __restrict__ bias, int n, bool act) {
    int warp = (blockIdx.x * blockDim.x + threadIdx.x) >> 5;
    int lane = threadIdx.x & 31;
    if (warp >= n) return;
    int i = warp;
    int start = d_rowptr[i], end = d_rowptr[i + 1];
    float dvi = d_dinv[i];
    float ax = 0.f, ay = 0.f;
    int j = start;
    for (; j + 4 <= end; j += 4) {
        int sA = d_col[j], sB = d_col[j + 1], sC = d_col[j + 2], sD = d_col[j + 3];
        float wA = d_dinv[sA], wB = d_dinv[sB], wC = d_dinv[sC], wD = d_dinv[sD];
        float2 vA = *(const float2*)(in + (size_t)sA * 64 + 2 * lane);
        float2 vB = *(const float2*)(in + (size_t)sB * 64 + 2 * lane);
        float2 vC = *(const float2*)(in + (size_t)sC * 64 + 2 * lane);
        float2 vD = *(const float2*)(in + (size_t)sD * 64 + 2 * lane);
        ax += wA * vA.x + wB * vB.x + wC * vC.x + wD * vD.x;
        ay += wA * vA.y + wB * vB.y + wC * vC.y + wD * vD.y;
    }
    for (; j < end; j++) {
        int s = d_col[j];
        float w = d_dinv[s];
        float2 v = *(const float2*)(in + (size_t)s * 64 + 2 * lane);
        ax += w * v.x; ay += w * v.y;
    }
    ax *= dvi; ay *= dvi;
    float2 o;
    if (act) {
        float2 b2 = *(const float2*)(bias + 2 * lane);
        o.x = lrelu(ax + b2.x, 0.01f);
        o.y = lrelu(ay + b2.y, 0.01f);
    } else {
        o.x = ax; o.y = ay;
    }
    *(float2*)(outp + (size_t)i * 64 + 2 * lane) = o;
}
__global__ void k_agg64_act(const float* __restrict__ bias, int n) {
    agg64_body(d_h2, d_g2, bias, n, true);     // g2 = lrelu(A@h2 + b2)
}
__global__ void k_agg64_plain(int n) {
    agg64_body(d_g2, d_h2, nullptr, n, false); // agg2 = A@g2 (reuse d_h2)
}

// ------- layer-3 matmul (64->128) + bias + lrelu + pool (register-tiled) -----
// block 256: 64 nodes/iter; thread = (cg 0..31 cols x4, ng = warp 0..7, 8 nodes)
__global__ void k_mm3pool(const float* __restrict__ W, const float* __restrict__ bias,
                          const int* __restrict__ batch, int n) {
    __shared__ float sW[64 * 128];
    __shared__ float sX[64 * 64];
    __shared__ float sb[128];
    __shared__ int sbt[64];
    const float4* W4 = (const float4*)W;
    float4* sW4 = (float4*)sW;
    for (int i = threadIdx.x; i < 64 * 128 / 4; i += 256) sW4[i] = W4[i];
    if (threadIdx.x < 128) sb[threadIdx.x] = bias[threadIdx.x];
    int cg = threadIdx.x & 31, ng = threadIdx.x >> 5;
    for (int base = blockIdx.x * 64; base < n; base += gridDim.x * 64) {
        __syncthreads();
        int cnt = min(64, n - base);
        {
            const float4* src = (const float4*)(d_h2 + (size_t)base * 64);
            float4* dst = (float4*)sX;
            int tot = cnt * 16;
            for (int i = threadIdx.x; i < tot; i += 256) dst[i] = src[i];
        }
        if (threadIdx.x < 64 && threadIdx.x < cnt) sbt[threadIdx.x] = batch[base + threadIdx.x];
        __syncthreads();
        float acc[8][4];
#pragma unroll
        for (int i = 0; i < 8; i++)
#pragma unroll
            for (int q = 0; q < 4; q++) acc[i][q] = 0.f;
        const float4* sWc = (const float4*)sW;
#pragma unroll 4
        for (int k = 0; k < 64; k++) {
            float4 w4 = sWc[k * 32 + cg];
#pragma unroll
            for (int i = 0; i < 8; i++) {
                float xv = sX[(ng * 8 + i) * 64 + k];
                acc[i][0] += xv * w4.x; acc[i][1] += xv * w4.y;
                acc[i][2] += xv * w4.z; acc[i][3] += xv * w4.w;
            }
        }
        float b0 = sb[cg * 4 + 0], b1 = sb[cg * 4 + 1], b2v = sb[cg * 4 + 2], b3v = sb[cg * 4 + 3];
#pragma unroll
        for (int i = 0; i < 8; i++) {
            int li = ng * 8 + i;
            int node = base + li;
            if (node < n) {
                float* pp = d_pool + (size_t)sbt[li] * 128 + cg * 4;
                atomicAdd(pp + 0, lrelu(acc[i][0] + b0, 0.01f));
                atomicAdd(pp + 1, lrelu(acc[i][1] + b1, 0.01f));
                atomicAdd(pp + 2, lrelu(acc[i][2] + b2v, 0.01f));
                atomicAdd(pp + 3, lrelu(acc[i][3] + b3v, 0.01f));
            }
        }
    }
}

// ---------------- global mean pool helpers -----------------------------------
__global__ void k_zero_pool(int b) {
    int i = blockIdx.x * blockDim.x + threadIdx.x;
    if (i < b * 128) d_pool[i] = 0.f;
    if (i < b) d_cntb[i] = 0.f;
}
__global__ void k_cntb(const int* __restrict__ batch, int n) {
    int i = blockIdx.x * blockDim.x + threadIdx.x;
    if (i < n) atomicAdd(&d_cntb[batch[i]], 1.f);
}
__global__ void k_pool_div(int b) {
    int i = blockIdx.x * blockDim.x + threadIdx.x;
    if (i < b * 128) d_pool[i] /= fmaxf(d_cntb[i >> 7], 1.f);
}

// ---------------- sequence branch -------------------------------------------
__global__ void k_conv1(const float* __restrict__ seq, const float* __restrict__ w,
                        const float* __restrict__ bconv,
                        const float* __restrict__ g, const float* __restrict__ be,
                        const float* __restrict__ m, const float* __restrict__ v, int b) {
    __shared__ float sw[64 * 30 * 3];
    for (int i = threadIdx.x; i < 64 * 30 * 3; i += 256) sw[i] = w[i];
    __syncthreads();
    int total = b * 64 * 18;
    for (int idx = blockIdx.x * blockDim.x + threadIdx.x; idx < total; idx += gridDim.x * blockDim.x) {
        int pos = idx % 18, co = (idx / 18) % 64, bb = idx / (18 * 64);
        float acc = bconv[co];
        const float* xb = seq + bb * (CH * SEQL);
        const float* wp = sw + co * 90;
#pragma unroll
        for (int cin = 0; cin < 30; cin++) {
            const float* xp = xb + cin * 20 + pos;
            acc += xp[0] * wp[cin * 3 + 0] + xp[1] * wp[cin * 3 + 1] + xp[2] * wp[cin * 3 + 2];
        }
        float sc = g[co] * rsqrtf(v[co] + 1e-5f);
        float sh = be[co] - m[co] * sc;
        d_s1[idx] = lrelu(acc * sc + sh, 0.01f);
    }
}
__global__ void k_conv2(const float* __restrict__ w, const float* __restrict__ bconv,
                        const float* __restrict__ g, const float* __restrict__ be,
                        const float* __restrict__ m, const float* __restrict__ v, int b) {
    __shared__ float sw[64 * 64 * 3];  // 48KB
    for (int i = threadIdx.x; i < 64 * 64 * 3; i += 256) sw[i] = w[i];
    __syncthreads();
    int total = b * 64 * 16;
    for (int idx = blockIdx.x * blockDim.x + threadIdx.x; idx < total; idx += gridDim.x * blockDim.x) {
        int pos = idx % 16, co = (idx / 16) % 64, bb = idx / (16 * 64);
        float acc = bconv[co];
        const float* xb = d_s1 + bb * (64 * 18);
        const float* wp = sw + co * 192;
#pragma unroll 8
        for (int cin = 0; cin < 64; cin++) {
            const float* xp = xb + cin * 18 + pos;
            acc += xp[0] * wp[cin * 3 + 0] + xp[1] * wp[cin * 3 + 1] + xp[2] * wp[cin * 3 + 2];
        }
        float sc = g[co] * rsqrtf(v[co] + 1e-5f);
        float sh = be[co] - m[co] * sc;
        d_s2[idx] = lrelu(acc * sc + sh, 0.01f);
    }
}

// fc1 as a tiled GEMM: [B,1024] @ [1024,64]  (64 rows per block)
__global__ void k_fc1g(const float* __restrict__ W, const float* __restrict__ bias, int b) {
    __shared__ float sX[64][65];
    __shared__ float sW[64][64];
    int c = threadIdx.x & 63, rg = threadIdx.x >> 6;  // rg in [0,4)
    int rowbase = blockIdx.x * 64;
    float acc[16];
#pragma unroll
    for (int r = 0; r < 16; r++) acc[r] = 0.f;
    for (int kt = 0; kt < 16; kt++) {
        __syncthreads();
        for (int i = threadIdx.x; i < 64 * 64; i += 256) {
            int r = i >> 6, k = i & 63;
            int row = rowbase + r;
            sX[r][k] = (row < b) ? d_s2[row * 1024 + kt * 64 + k] : 0.f;
        }
        for (int i = threadIdx.x; i < 64 * 64; i += 256) {
            int k = i >> 6, cc = i & 63;
            sW[k][cc] = W[(kt * 64 + k) * 64 + cc];
        }
        __syncthreads();
#pragma unroll
        for (int k = 0; k < 64; k++) {
            float w = sW[k][c];
#pragma unroll
            for (int r = 0; r < 16; r++) acc[r] += sX[rg * 16 + r][k] * w;
        }
    }
    float bb = bias[c];
#pragma unroll
    for (int r = 0; r < 16; r++) {
        int row = rowbase + rg * 16 + r;
        if (row < b) d_sfc[row * 64 + c] = acc[r] + bb;
    }
}

// ---------------- fusion + classifier (4 graphs per block) -------------------
__global__ void k_head(const float* __restrict__ fusW, const float* __restrict__ fusb,
                       const float* __restrict__ c1W, const float* __restrict__ c1b,
                       const float* __restrict__ c3W, const float* __restrict__ c3b,
                       float* __restrict__ out, int b) {
    __shared__ float comb[4][192];
    __shared__ float t1[4][128];
    __shared__ float red[4][2];
    int tid = threadIdx.x;
    int b0 = blockIdx.x * 4;
    int nb = min(4, b - b0);
#pragma unroll
    for (int g = 0; g < 4; g++) {
        if (g < nb) {
            comb[g][tid] = d_pool[(b0 + g) * 128 + tid];
            if (tid < 64) comb[g][128 + tid] = d_sfc[(b0 + g) * 64 + tid];
        }
    }
    __syncthreads();
    float a0 = fusb[tid], a1 = a0, a2 = a0, a3 = a0;
    for (int k = 0; k < 192; k++) {
        float w = fusW[k * 128 + tid];
        a0 += comb[0][k] * w; a1 += comb[1][k] * w;
        a2 += comb[2][k] * w; a3 += comb[3][k] * w;
    }
    t1[0][tid] = lrelu(a0, 0.01f); t1[1][tid] = lrelu(a1, 0.01f);
    t1[2][tid] = lrelu(a2, 0.01f); t1[3][tid] = lrelu(a3, 0.01f);
    __syncthreads();
    if (tid < 64) {
        float q0 = c1b[tid], q1 = q0, q2 = q0, q3 = q0;
        for (int k = 0; k < 128; k++) {
            float w = c1W[k * 64 + tid];
            q0 += t1[0][k] * w; q1 += t1[1][k] * w;
            q2 += t1[2][k] * w; q3 += t1[3][k] * w;
        }
        float wc = c3W[tid];
        float v0 = lrelu(q0, 0.01f) * wc;
        float v1 = lrelu(q1, 0.01f) * wc;
        float v2 = lrelu(q2, 0.01f) * wc;
        float v3 = lrelu(q3, 0.01f) * wc;
        v0 = warpSum(v0); v1 = warpSum(v1); v2 = warpSum(v2); v3 = warpSum(v3);
        if ((tid & 31) == 0) {
            int h = tid >> 5;
            red[0][h] = v0; red[1][h] = v1; red[2][h] = v2; red[3][h] = v3;
        }
    }
    __syncthreads();
    if (tid < 4 && tid < nb) out[b0 + tid] = red[tid][0] + red[tid][1] + c3b[0];
}

// ---------------- launch ------------------------------------------------------
extern "C" void kernel_launch(void* const* d_in, const int* in_sizes, int n_in,
                              void* d_out, int out_size) {
    const float* x      = (const float*)d_in[0];
    const int*   ei     = (const int*)d_in[1];
    const int*   batch  = (const int*)d_in[2];
    const float* seq    = (const float*)d_in[3];
    const float* W_gat  = (const float*)d_in[4];
    const float* att_s  = (const float*)d_in[5];
    const float* att_d  = (const float*)d_in[6];
    const float* b_gat  = (const float*)d_in[7];
    const float* W2     = (const float*)d_in[8];
    const float* b2     = (const float*)d_in[9];
    const float* W3     = (const float*)d_in[10];
    const float* b3     = (const float*)d_in[11];
    const float* c1w    = (const float*)d_in[12];
    const float* c1b    = (const float*)d_in[13];
    const float* c2w    = (const float*)d_in[14];
    const float* c2b    = (const float*)d_in[15];
    const float* bn1g   = (const float*)d_in[16];
    const float* bn1b   = (const float*)d_in[17];
    const float* bn1m   = (const float*)d_in[18];
    const float* bn1v   = (const float*)d_in[19];
    const float* bn2g   = (const float*)d_in[20];
    const float* bn2b   = (const float*)d_in[21];
    const float* bn2m   = (const float*)d_in[22];
    const float* bn2v   = (const float*)d_in[23];
    const float* fc1W   = (const float*)d_in[24];
    const float* fc1b   = (const float*)d_in[25];
    const float* fusW   = (const float*)d_in[26];
    const float* fusb   = (const float*)d_in[27];
    const float* cl1W   = (const float*)d_in[28];
    const float* cl1b   = (const float*)d_in[29];
    const float* cl3W   = (const float*)d_in[30];
    const float* cl3b   = (const float*)d_in[31];
    float* out = (float*)d_out;

    int n = in_sizes[0] / 9;
    int E = in_sizes[1] / 2;
    int b = in_sizes[3] / (CH * SEQL);
    if (n > MAXN || E > MAXE || b > BSZ) return;

    // sequence branch + GAT node transform + pool init (single stream)
    k_conv1<<<512, 256>>>(seq, c1w, c1b, bn1g, bn1b, bn1m, bn1v, b);
    k_conv2<<<512, 256>>>(c2w, c2b, bn2g, bn2b, bn2m, bn2v, b);
    k_fc1g<<<(b + 63) / 64, 256>>>(fc1W, fc1b, b);
    k_gat_node<<<(n + 15) / 16, 128>>>(x, W_gat, att_s, att_d, n);
    k_zero_pool<<<(b * 128 + 255) / 256, 256>>>(b);
    k_cntb<<<(n + 255) / 256, 256>>>(batch, n);

    // CSR build
    k_deg_init<<<(n + 255) / 256, 256>>>(n);
    k_count<<<2048, 256>>>(ei, E);
    int NB = (n + 511) / 512;
    k_scan1<<<NB, 512>>>(n);
    k_scan2<<<1, 512>>>(NB);
    k_scan3<<<NB, 512>>>(n, E + n);
    k_selfloop<<<(n + 255) / 256, 256>>>(n);
    k_scatter<<<2048, 256>>>(ei, E);

    // GAT aggregate -> g1
    k_gat_agg<<<(n + 7) / 8, 256>>>(b_gat, n);

    // GCN layer 2: h2 = g1@W2 ; g2 = lrelu(A@h2 + b2)
    k_mm1<<<592, 256>>>(W2, n);
    k_agg64_act<<<(n + 7) / 8, 256>>>(b2, n);

    // GCN layer 3 (linearity): agg2 = A@g2 (64-dim), then
    // per-node out = lrelu(agg2@W3 + b3) accumulated straight into the pool
    k_agg64_plain<<<(n + 7) / 8, 256>>>(n);
    k_mm3pool<<<592, 256>>>(W3, b3, batch, n);
    k_pool_div<<<(b * 128 + 255) / 256, 256>>>(b);

    // fusion + classifier
    k_head<<<(b + 3) / 4, 128>>>(fusW, fusb, cl1W, cl1b, cl3W, cl3b, out, b);
}

// round 9
// speedup vs baseline: 1.2552x; 1.0077x over previous
#include <cuda_runtime.h>
#include <cuda_fp16.h>
#include <math.h>
#include <stdint.h>

// Problem constants (fixed by the dataset)
#define MAXN 100000
#define MAXE 1600000
#define MAXT (MAXN + MAXE)
#define BSZ  1024
#define CH   30
#define SEQL 20

// ---------------- scratch (static device globals; no allocation) -------------
__device__ __half d_h[(size_t)MAXN * 128];   // GAT h (fp16 storage)
__device__ float  d_g1[(size_t)MAXN * 128];  // GAT out g1 (fp32)
__device__ __half d_h2[(size_t)MAXN * 64];   // h2 = g1@W2 (fp16)
__device__ __half d_g2[(size_t)MAXN * 64];   // g2 (fp16)
__device__ float  d_agg[(size_t)MAXN * 64];  // A@g2 (fp32)
__device__ float d_as[MAXN * 4];
__device__ float d_ad[MAXN * 4];
__device__ int   d_deg[MAXN];
__device__ int   d_rowptr[MAXN + 1];
__device__ int   d_cursor[MAXN];
__device__ int   d_col[MAXT];
__device__ int   d_bsums[1024];
__device__ float d_dinv[MAXN];
__device__ float d_pool[BSZ * 128];
__device__ float d_cntb[BSZ];
__device__ float d_s1[BSZ * 64 * 18];
__device__ float d_s2[BSZ * 64 * 16];
__device__ float d_sfc[BSZ * 64];

__device__ __forceinline__ float lrelu(float x, float s) { return x >= 0.f ? x : s * x; }
__device__ __forceinline__ float warpMax(float v) {
#pragma unroll
    for (int o = 16; o > 0; o >>= 1) v = fmaxf(v, __shfl_xor_sync(0xffffffffu, v, o));
    return v;
}
__device__ __forceinline__ float warpSum(float v) {
#pragma unroll
    for (int o = 16; o > 0; o >>= 1) v += __shfl_xor_sync(0xffffffffu, v, o);
    return v;
}
__device__ __forceinline__ float sum8(float v) {
#pragma unroll
    for (int o = 4; o > 0; o >>= 1) v += __shfl_xor_sync(0xffffffffu, v, o);
    return v;
}

// fp16 vector helpers (load -> fp32 math)
__device__ __forceinline__ float4 ldh4(const __half* p) {
    uint2 u = *(const uint2*)p;
    __half2 a = *reinterpret_cast<__half2*>(&u.x);
    __half2 b = *reinterpret_cast<__half2*>(&u.y);
    float2 fa = __half22float2(a), fb = __half22float2(b);
    return make_float4(fa.x, fa.y, fb.x, fb.y);
}
__device__ __forceinline__ float2 ldh2(const __half* p) {
    return __half22float2(*(const __half2*)p);
}
__device__ __forceinline__ void sth4(__half* p, float4 v) {
    __half2 a = __floats2half2_rn(v.x, v.y);
    __half2 b = __floats2half2_rn(v.z, v.w);
    uint2 u;
    u.x = *reinterpret_cast<unsigned*>(&a);
    u.y = *reinterpret_cast<unsigned*>(&b);
    *(uint2*)p = u;
}
__device__ __forceinline__ void sth2(__half* p, float2 v) {
    *(__half2*)p = __floats2half2_rn(v.x, v.y);
}

// ---------------- K1: h = x @ W_gat ; a_s, a_d ------------------------------
// block 128 = 4 node-lanes x 32 col-groups; 16 nodes per block; thread owns 4 ch
__global__ void k_gat_node(const float* __restrict__ x, const float* __restrict__ Wg,
                           const float* __restrict__ asrc, const float* __restrict__ adst, int n) {
    int lane = threadIdx.x & 31;   // column group: channels 4*lane .. 4*lane+3
    int wid  = threadIdx.x >> 5;   // node-lane 0..3
    float w[9][4];
#pragma unroll
    for (int f = 0; f < 9; f++)
#pragma unroll
        for (int q = 0; q < 4; q++) w[f][q] = Wg[f * 128 + 4 * lane + q];
    float atts[4], attd[4];
#pragma unroll
    for (int q = 0; q < 4; q++) { atts[q] = asrc[4 * lane + q]; attd[q] = adst[4 * lane + q]; }
    __shared__ float sx[16 * 9];
    int base = blockIdx.x * 16;
    int cnt = min(16, n - base);
    if (cnt <= 0) return;
    for (int i = threadIdx.x; i < cnt * 9; i += 128) sx[i] = x[base * 9 + i];
    __syncthreads();
    int hh = lane >> 3;  // head
#pragma unroll
    for (int t = 0; t < 4; t++) {
        int li = t * 4 + wid;
        int node = base + li;
        if (li >= cnt) break;
        float h[4] = {0.f, 0.f, 0.f, 0.f};
#pragma unroll
        for (int f = 0; f < 9; f++) {
            float xv = sx[li * 9 + f];
#pragma unroll
            for (int q = 0; q < 4; q++) h[q] += xv * w[f][q];
        }
        float ps = h[0] * atts[0] + h[1] * atts[1] + h[2] * atts[2] + h[3] * atts[3];
        float pd = h[0] * attd[0] + h[1] * attd[1] + h[2] * attd[2] + h[3] * attd[3];
        ps = sum8(ps); pd = sum8(pd);
        if ((lane & 7) == 0) {
            d_as[node * 4 + hh] = ps;
            d_ad[node * 4 + hh] = pd;
        }
        sth4(d_h + (size_t)node * 128 + 4 * lane, make_float4(h[0], h[1], h[2], h[3]));
    }
}

// ---------------- CSR build --------------------------------------------------
__global__ void k_deg_init(int n) {
    int i = blockIdx.x * blockDim.x + threadIdx.x;
    if (i < n) d_deg[i] = 1;  // self loop
}
__global__ void k_count(const int* __restrict__ ei, int E) {
    for (int e = blockIdx.x * blockDim.x + threadIdx.x; e < E; e += gridDim.x * blockDim.x)
        atomicAdd(&d_deg[ei[E + e]], 1);
}
__global__ void k_scan1(int n) {
    __shared__ int ss[512];
    int idx = blockIdx.x * 512 + threadIdx.x;
    int val = (idx < n) ? d_deg[idx] : 0;
    ss[threadIdx.x] = val;
    __syncthreads();
#pragma unroll
    for (int off = 1; off < 512; off <<= 1) {
        int t = (threadIdx.x >= off) ? ss[threadIdx.x - off] : 0;
        __syncthreads();
        ss[threadIdx.x] += t;
        __syncthreads();
    }
    if (idx < n) d_rowptr[idx] = ss[threadIdx.x] - val;  // exclusive
    if (threadIdx.x == 511) d_bsums[blockIdx.x] = ss[511];
}
__global__ void k_scan2(int nb) {
    __shared__ int ss[512];
    int v = (threadIdx.x < nb) ? d_bsums[threadIdx.x] : 0;
    ss[threadIdx.x] = v;
    __syncthreads();
#pragma unroll
    for (int off = 1; off < 512; off <<= 1) {
        int t = (threadIdx.x >= off) ? ss[threadIdx.x - off] : 0;
        __syncthreads();
        ss[threadIdx.x] += t;
        __syncthreads();
    }
    if (threadIdx.x < nb) d_bsums[threadIdx.x] = ss[threadIdx.x] - v;  // exclusive
}
__global__ void k_scan3(int n, int tot) {
    int idx = blockIdx.x * 512 + threadIdx.x;
    if (idx < n) d_rowptr[idx] += d_bsums[blockIdx.x];
    if (idx == 0) d_rowptr[n] = tot;
}
__global__ void k_selfloop(int n) {
    int i = blockIdx.x * blockDim.x + threadIdx.x;
    if (i < n) {
        int p = d_rowptr[i];
        d_col[p] = i;
        d_cursor[i] = p + 1;
        d_dinv[i] = rsqrtf((float)d_deg[i]);
    }
}
__global__ void k_scatter(const int* __restrict__ ei, int E) {
    for (int e = blockIdx.x * blockDim.x + threadIdx.x; e < E; e += gridDim.x * blockDim.x) {
        int s = ei[e], d = ei[E + e];
        int pos = atomicAdd(&d_cursor[d], 1);
        d_col[pos] = s;
    }
}

// ---------------- GAT aggregate (one warp per dst node, online softmax) ------
__global__ void k_gat_agg(const float* __restrict__ bias, int n) {
    int warp = (blockIdx.x * blockDim.x + threadIdx.x) >> 5;
    int lane = threadIdx.x & 31;
    if (warp >= n) return;
    int i = warp;
    int start = d_rowptr[i], end = d_rowptr[i + 1];
    float4 ad4 = *(const float4*)(d_ad + 4 * i);
    float m0 = -1e30f, m1 = -1e30f, m2 = -1e30f, m3 = -1e30f;
    float s0 = 0.f, s1 = 0.f, s2 = 0.f, s3 = 0.f;
    for (int j = start + lane; j < end; j += 32) {
        int s = d_col[j];
        float4 a = *(const float4*)(d_as + 4 * s);
        float e0 = lrelu(a.x + ad4.x, 0.2f);
        float e1 = lrelu(a.y + ad4.y, 0.2f);
        float e2 = lrelu(a.z + ad4.z, 0.2f);
        float e3 = lrelu(a.w + ad4.w, 0.2f);
        if (e0 <= m0) s0 += expf(e0 - m0); else { s0 = s0 * expf(m0 - e0) + 1.f; m0 = e0; }
        if (e1 <= m1) s1 += expf(e1 - m1); else { s1 = s1 * expf(m1 - e1) + 1.f; m1 = e1; }
        if (e2 <= m2) s2 += expf(e2 - m2); else { s2 = s2 * expf(m2 - e2) + 1.f; m2 = e2; }
        if (e3 <= m3) s3 += expf(e3 - m3); else { s3 = s3 * expf(m3 - e3) + 1.f; m3 = e3; }
    }
    float M0 = warpMax(m0), M1 = warpMax(m1), M2 = warpMax(m2), M3 = warpMax(m3);
    s0 = warpSum(s0 * expf(m0 - M0));
    s1 = warpSum(s1 * expf(m1 - M1));
    s2 = warpSum(s2 * expf(m2 - M2));
    s3 = warpSum(s3 * expf(m3 - M3));
    float i0 = 1.f / (s0 + 1e-16f), i1 = 1.f / (s1 + 1e-16f);
    float i2 = 1.f / (s2 + 1e-16f), i3 = 1.f / (s3 + 1e-16f);
    int hh = lane >> 3;  // head of this lane's 4 channels
    float mm = hh < 2 ? (hh == 0 ? M0 : M1) : (hh == 2 ? M2 : M3);
    float ii = hh < 2 ? (hh == 0 ? i0 : i1) : (hh == 2 ? i2 : i3);
    float aad = hh < 2 ? (hh == 0 ? ad4.x : ad4.y) : (hh == 2 ? ad4.z : ad4.w);
    float4 acc = make_float4(0.f, 0.f, 0.f, 0.f);
    int j = start;
    for (; j + 4 <= end; j += 4) {
        int sA = d_col[j], sB = d_col[j + 1], sC = d_col[j + 2], sD = d_col[j + 3];
        float4 aA = *(const float4*)(d_as + 4 * sA);
        float4 aB = *(const float4*)(d_as + 4 * sB);
        float4 aC = *(const float4*)(d_as + 4 * sC);
        float4 aD = *(const float4*)(d_as + 4 * sD);
        const float4 hA = ldh4(d_h + (size_t)sA * 128 + 4 * lane);
        const float4 hB = ldh4(d_h + (size_t)sB * 128 + 4 * lane);
        const float4 hC = ldh4(d_h + (size_t)sC * 128 + 4 * lane);
        const float4 hD = ldh4(d_h + (size_t)sD * 128 + 4 * lane);
        float avA = hh < 2 ? (hh == 0 ? aA.x : aA.y) : (hh == 2 ? aA.z : aA.w);
        float avB = hh < 2 ? (hh == 0 ? aB.x : aB.y) : (hh == 2 ? aB.z : aB.w);
        float avC = hh < 2 ? (hh == 0 ? aC.x : aC.y) : (hh == 2 ? aC.z : aC.w);
        float avD = hh < 2 ? (hh == 0 ? aD.x : aD.y) : (hh == 2 ? aD.z : aD.w);
        float alA = expf(lrelu(avA + aad, 0.2f) - mm) * ii;
        float alB = expf(lrelu(avB + aad, 0.2f) - mm) * ii;
        float alC = expf(lrelu(avC + aad, 0.2f) - mm) * ii;
        float alD = expf(lrelu(avD + aad, 0.2f) - mm) * ii;
        acc.x += alA * hA.x + alB * hB.x + alC * hC.x + alD * hD.x;
        acc.y += alA * hA.y + alB * hB.y + alC * hC.y + alD * hD.y;
        acc.z += alA * hA.z + alB * hB.z + alC * hC.z + alD * hD.z;
        acc.w += alA * hA.w + alB * hB.w + alC * hC.w + alD * hD.w;
    }
    for (; j < end; j++) {
        int s = d_col[j];
        float4 a = *(const float4*)(d_as + 4 * s);
        float av = hh < 2 ? (hh == 0 ? a.x : a.y) : (hh == 2 ? a.z : a.w);
        float alpha = expf(lrelu(av + aad, 0.2f) - mm) * ii;
        const float4 hv = ldh4(d_h + (size_t)s * 128 + 4 * lane);
        acc.x += alpha * hv.x; acc.y += alpha * hv.y;
        acc.z += alpha * hv.z; acc.w += alpha * hv.w;
    }
    float4 b4 = *(const float4*)(bias + 4 * lane);
    float4 o;
    o.x = lrelu(acc.x + b4.x, 0.01f);
    o.y = lrelu(acc.y + b4.y, 0.01f);
    o.z = lrelu(acc.z + b4.z, 0.01f);
    o.w = lrelu(acc.w + b4.w, 0.01f);
    *(float4*)(d_g1 + (size_t)i * 128 + 4 * lane) = o;
}

// ---------------- h2 = g1[N,128] @ W2[128,64]  (register-tiled, fp16 out) ----
__global__ void k_mm1(const float* __restrict__ W, int n) {
    __shared__ float sW[128 * 64];
    __shared__ float sX[64 * 128];
    const float4* W4 = (const float4*)W;
    float4* sW4 = (float4*)sW;
    for (int i = threadIdx.x; i < 128 * 64 / 4; i += 256) sW4[i] = W4[i];
    int cg = threadIdx.x & 15, ng = threadIdx.x >> 4;
    for (int base = blockIdx.x * 64; base < n; base += gridDim.x * 64) {
        __syncthreads();
        int cnt = min(64, n - base);
        {
            const float4* src = (const float4*)(d_g1 + (size_t)base * 128);
            float4* dst = (float4*)sX;
            int tot = cnt * 32;
            for (int i = threadIdx.x; i < tot; i += 256) dst[i] = src[i];
        }
        __syncthreads();
        float acc[4][4];
#pragma unroll
        for (int i = 0; i < 4; i++)
#pragma unroll
            for (int q = 0; q < 4; q++) acc[i][q] = 0.f;
        const float4* sWc = (const float4*)sW;
#pragma unroll 4
        for (int k = 0; k < 128; k++) {
            float4 w4 = sWc[k * 16 + cg];
#pragma unroll
            for (int i = 0; i < 4; i++) {
                float xv = sX[(ng * 4 + i) * 128 + k];
                acc[i][0] += xv * w4.x; acc[i][1] += xv * w4.y;
                acc[i][2] += xv * w4.z; acc[i][3] += xv * w4.w;
            }
        }
#pragma unroll
        for (int i = 0; i < 4; i++) {
            int node = base + ng * 4 + i;
            if (node < n)
                sth4(d_h2 + (size_t)node * 64 + cg * 4,
                     make_float4(acc[i][0], acc[i][1], acc[i][2], acc[i][3]));
        }
    }
}

// ---------------- 64-dim GCN aggregation (warp per dst, unroll 4, fp16 in) ---
// g2 = lrelu(A@h2 + b2)   (fp16 in, fp16 out)
__global__ void k_agg64_act(const float* __restrict__ bias, int n) {
    int warp = (blockIdx.x * blockDim.x + threadIdx.x) >> 5;
    int lane = threadIdx.x & 31;
    if (warp >= n) return;
    int i = warp;
    int start = d_rowptr[i], end = d_rowptr[i + 1];
    float dvi = d_dinv[i];
    float ax = 0.f, ay = 0.f;
    int j = start;
    for (; j + 4 <= end; j += 4) {
        int sA = d_col[j], sB = d_col[j + 1], sC = d_col[j + 2], sD = d_col[j + 3];
        float wA = d_dinv[sA], wB = d_dinv[sB], wC = d_dinv[sC], wD = d_dinv[sD];
        float2 vA = ldh2(d_h2 + (size_t)sA * 64 + 2 * lane);
        float2 vB = ldh2(d_h2 + (size_t)sB * 64 + 2 * lane);
        float2 vC = ldh2(d_h2 + (size_t)sC * 64 + 2 * lane);
        float2 vD = ldh2(d_h2 + (size_t)sD * 64 + 2 * lane);
        ax += wA * vA.x + wB * vB.x + wC * vC.x + wD * vD.x;
        ay += wA * vA.y + wB * vB.y + wC * vC.y + wD * vD.y;
    }
    for (; j < end; j++) {
        int s = d_col[j];
        float w = d_dinv[s];
        float2 v = ldh2(d_h2 + (size_t)s * 64 + 2 * lane);
        ax += w * v.x; ay += w * v.y;
    }
    ax *= dvi; ay *= dvi;
    float2 b2 = *(const float2*)(bias + 2 * lane);
    sth2(d_g2 + (size_t)i * 64 + 2 * lane,
         make_float2(lrelu(ax + b2.x, 0.01f), lrelu(ay + b2.y, 0.01f)));
}
// agg = A@g2   (fp16 in, fp32 out)
__global__ void k_agg64_plain(int n) {
    int warp = (blockIdx.x * blockDim.x + threadIdx.x) >> 5;
    int lane = threadIdx.x & 31;
    if (warp >= n) return;
    int i = warp;
    int start = d_rowptr[i], end = d_rowptr[i + 1];
    float dvi = d_dinv[i];
    float ax = 0.f, ay = 0.f;
    int j = start;
    for (; j + 4 <= end; j += 4) {
        int sA = d_col[j], sB = d_col[j + 1], sC = d_col[j + 2], sD = d_col[j + 3];
        float wA = d_dinv[sA], wB = d_dinv[sB], wC = d_dinv[sC], wD = d_dinv[sD];
        float2 vA = ldh2(d_g2 + (size_t)sA * 64 + 2 * lane);
        float2 vB = ldh2(d_g2 + (size_t)sB * 64 + 2 * lane);
        float2 vC = ldh2(d_g2 + (size_t)sC * 64 + 2 * lane);
        float2 vD = ldh2(d_g2 + (size_t)sD * 64 + 2 * lane);
        ax += wA * vA.x + wB * vB.x + wC * vC.x + wD * vD.x;
        ay += wA * vA.y + wB * vB.y + wC * vC.y + wD * vD.y;
    }
    for (; j < end; j++) {
        int s = d_col[j];
        float w = d_dinv[s];
        float2 v = ldh2(d_g2 + (size_t)s * 64 + 2 * lane);
        ax += w * v.x; ay += w * v.y;
    }
    *(float2*)(d_agg + (size_t)i * 64 + 2 * lane) = make_float2(ax * dvi, ay * dvi);
}

// ------- layer-3 matmul (64->128) + bias + lrelu + pool (register-tiled) -----
__global__ void k_mm3pool(const float* __restrict__ W, const float* __restrict__ bias,
                          const int* __restrict__ batch, int n) {
    __shared__ float sW[64 * 128];
    __shared__ float sX[64 * 64];
    __shared__ float sb[128];
    __shared__ int sbt[64];
    const float4* W4 = (const float4*)W;
    float4* sW4 = (float4*)sW;
    for (int i = threadIdx.x; i < 64 * 128 / 4; i += 256) sW4[i] = W4[i];
    if (threadIdx.x < 128) sb[threadIdx.x] = bias[threadIdx.x];
    int cg = threadIdx.x & 31, ng = threadIdx.x >> 5;
    for (int base = blockIdx.x * 64; base < n; base += gridDim.x * 64) {
        __syncthreads();
        int cnt = min(64, n - base);
        {
            const float4* src = (const float4*)(d_agg + (size_t)base * 64);
            float4* dst = (float4*)sX;
            int tot = cnt * 16;
            for (int i = threadIdx.x; i < tot; i += 256) dst[i] = src[i];
        }
        if (threadIdx.x < 64 && threadIdx.x < cnt) sbt[threadIdx.x] = batch[base + threadIdx.x];
        __syncthreads();
        float acc[8][4];
#pragma unroll
        for (int i = 0; i < 8; i++)
#pragma unroll
            for (int q = 0; q < 4; q++) acc[i][q] = 0.f;
        const float4* sWc = (const float4*)sW;
#pragma unroll 4
        for (int k = 0; k < 64; k++) {
            float4 w4 = sWc[k * 32 + cg];
#pragma unroll
            for (int i = 0; i < 8; i++) {
                float xv = sX[(ng * 8 + i) * 64 + k];
                acc[i][0] += xv * w4.x; acc[i][1] += xv * w4.y;
                acc[i][2] += xv * w4.z; acc[i][3] += xv * w4.w;
            }
        }
        float b0 = sb[cg * 4 + 0], b1 = sb[cg * 4 + 1], b2v = sb[cg * 4 + 2], b3v = sb[cg * 4 + 3];
#pragma unroll
        for (int i = 0; i < 8; i++) {
            int li = ng * 8 + i;
            int node = base + li;
            if (node < n) {
                float* pp = d_pool + (size_t)sbt[li] * 128 + cg * 4;
                atomicAdd(pp + 0, lrelu(acc[i][0] + b0, 0.01f));
                atomicAdd(pp + 1, lrelu(acc[i][1] + b1, 0.01f));
                atomicAdd(pp + 2, lrelu(acc[i][2] + b2v, 0.01f));
                atomicAdd(pp + 3, lrelu(acc[i][3] + b3v, 0.01f));
            }
        }
    }
}

// ---------------- global mean pool helpers -----------------------------------
__global__ void k_zero_pool(int b) {
    int i = blockIdx.x * blockDim.x + threadIdx.x;
    if (i < b * 128) d_pool[i] = 0.f;
    if (i < b) d_cntb[i] = 0.f;
}
__global__ void k_cntb(const int* __restrict__ batch, int n) {
    int i = blockIdx.x * blockDim.x + threadIdx.x;
    if (i < n) atomicAdd(&d_cntb[batch[i]], 1.f);
}
__global__ void k_pool_div(int b) {
    int i = blockIdx.x * blockDim.x + threadIdx.x;
    if (i < b * 128) d_pool[i] /= fmaxf(d_cntb[i >> 7], 1.f);
}

// ---------------- sequence branch -------------------------------------------
__global__ void k_conv1(const float* __restrict__ seq, const float* __restrict__ w,
                        const float* __restrict__ bconv,
                        const float* __restrict__ g, const float* __restrict__ be,
                        const float* __restrict__ m, const float* __restrict__ v, int b) {
    __shared__ float sw[64 * 30 * 3];
    for (int i = threadIdx.x; i < 64 * 30 * 3; i += 256) sw[i] = w[i];
    __syncthreads();
    int total = b * 64 * 18;
    for (int idx = blockIdx.x * blockDim.x + threadIdx.x; idx < total; idx += gridDim.x * blockDim.x) {
        int pos = idx % 18, co = (idx / 18) % 64, bb = idx / (18 * 64);
        float acc = bconv[co];
        const float* xb = seq + bb * (CH * SEQL);
        const float* wp = sw + co * 90;
#pragma unroll
        for (int cin = 0; cin < 30; cin++) {
            const float* xp = xb + cin * 20 + pos;
            acc += xp[0] * wp[cin * 3 + 0] + xp[1] * wp[cin * 3 + 1] + xp[2] * wp[cin * 3 + 2];
        }
        float sc = g[co] * rsqrtf(v[co] + 1e-5f);
        float sh = be[co] - m[co] * sc;
        d_s1[idx] = lrelu(acc * sc + sh, 0.01f);
    }
}
__global__ void k_conv2(const float* __restrict__ w, const float* __restrict__ bconv,
                        const float* __restrict__ g, const float* __restrict__ be,
                        const float* __restrict__ m, const float* __restrict__ v, int b) {
    __shared__ float sw[64 * 64 * 3];  // 48KB
    for (int i = threadIdx.x; i < 64 * 64 * 3; i += 256) sw[i] = w[i];
    __syncthreads();
    int total = b * 64 * 16;
    for (int idx = blockIdx.x * blockDim.x + threadIdx.x; idx < total; idx += gridDim.x * blockDim.x) {
        int pos = idx % 16, co = (idx / 16) % 64, bb = idx / (16 * 64);
        float acc = bconv[co];
        const float* xb = d_s1 + bb * (64 * 18);
        const float* wp = sw + co * 192;
#pragma unroll 8
        for (int cin = 0; cin < 64; cin++) {
            const float* xp = xb + cin * 18 + pos;
            acc += xp[0] * wp[cin * 3 + 0] + xp[1] * wp[cin * 3 + 1] + xp[2] * wp[cin * 3 + 2];
        }
        float sc = g[co] * rsqrtf(v[co] + 1e-5f);
        float sh = be[co] - m[co] * sc;
        d_s2[idx] = lrelu(acc * sc + sh, 0.01f);
    }
}

// fc1 as a tiled GEMM: [B,1024] @ [1024,64]  (64 rows per block)
__global__ void k_fc1g(const float* __restrict__ W, const float* __restrict__ bias, int b) {
    __shared__ float sX[64][65];
    __shared__ float sW[64][64];
    int c = threadIdx.x & 63, rg = threadIdx.x >> 6;  // rg in [0,4)
    int rowbase = blockIdx.x * 64;
    float acc[16];
#pragma unroll
    for (int r = 0; r < 16; r++) acc[r] = 0.f;
    for (int kt = 0; kt < 16; kt++) {
        __syncthreads();
        for (int i = threadIdx.x; i < 64 * 64; i += 256) {
            int r = i >> 6, k = i & 63;
            int row = rowbase + r;
            sX[r][k] = (row < b) ? d_s2[row * 1024 + kt * 64 + k] : 0.f;
        }
        for (int i = threadIdx.x; i < 64 * 64; i += 256) {
            int k = i >> 6, cc = i & 63;
            sW[k][cc] = W[(kt * 64 + k) * 64 + cc];
        }
        __syncthreads();
#pragma unroll
        for (int k = 0; k < 64; k++) {
            float w = sW[k][c];
#pragma unroll
            for (int r = 0; r < 16; r++) acc[r] += sX[rg * 16 + r][k] * w;
        }
    }
    float bb = bias[c];
#pragma unroll
    for (int r = 0; r < 16; r++) {
        int row = rowbase + rg * 16 + r;
        if (row < b) d_sfc[row * 64 + c] = acc[r] + bb;
    }
}

// ---------------- fusion + classifier (4 graphs per block) -------------------
__global__ void k_head(const float* __restrict__ fusW, const float* __restrict__ fusb,
                       const float* __restrict__ c1W, const float* __restrict__ c1b,
                       const float* __restrict__ c3W, const float* __restrict__ c3b,
                       float* __restrict__ out, int b) {
    __shared__ float comb[4][192];
    __shared__ float t1[4][128];
    __shared__ float red[4][2];
    int tid = threadIdx.x;
    int b0 = blockIdx.x * 4;
    int nb = min(4, b - b0);
#pragma unroll
    for (int g = 0; g < 4; g++) {
        if (g < nb) {
            comb[g][tid] = d_pool[(b0 + g) * 128 + tid];
            if (tid < 64) comb[g][128 + tid] = d_sfc[(b0 + g) * 64 + tid];
        }
    }
    __syncthreads();
    float a0 = fusb[tid], a1 = a0, a2 = a0, a3 = a0;
    for (int k = 0; k < 192; k++) {
        float w = fusW[k * 128 + tid];
        a0 += comb[0][k] * w; a1 += comb[1][k] * w;
        a2 += comb[2][k] * w; a3 += comb[3][k] * w;
    }
    t1[0][tid] = lrelu(a0, 0.01f); t1[1][tid] = lrelu(a1, 0.01f);
    t1[2][tid] = lrelu(a2, 0.01f); t1[3][tid] = lrelu(a3, 0.01f);
    __syncthreads();
    if (tid < 64) {
        float q0 = c1b[tid], q1 = q0, q2 = q0, q3 = q0;
        for (int k = 0; k < 128; k++) {
            float w = c1W[k * 64 + tid];
            q0 += t1[0][k] * w; q1 += t1[1][k] * w;
            q2 += t1[2][k] * w; q3 += t1[3][k] * w;
        }
        float wc = c3W[tid];
        float v0 = lrelu(q0, 0.01f) * wc;
        float v1 = lrelu(q1, 0.01f) * wc;
        float v2 = lrelu(q2, 0.01f) * wc;
        float v3 = lrelu(q3, 0.01f) * wc;
        v0 = warpSum(v0); v1 = warpSum(v1); v2 = warpSum(v2); v3 = warpSum(v3);
        if ((tid & 31) == 0) {
            int h = tid >> 5;
            red[0][h] = v0; red[1][h] = v1; red[2][h] = v2; red[3][h] = v3;
        }
    }
    __syncthreads();
    if (tid < 4 && tid < nb) out[b0 + tid] = red[tid][0] + red[tid][1] + c3b[0];
}

// ---------------- launch ------------------------------------------------------
extern "C" void kernel_launch(void* const* d_in, const int* in_sizes, int n_in,
                              void* d_out, int out_size) {
    const float* x      = (const float*)d_in[0];
    const int*   ei     = (const int*)d_in[1];
    const int*   batch  = (const int*)d_in[2];
    const float* seq    = (const float*)d_in[3];
    const float* W_gat  = (const float*)d_in[4];
    const float* att_s  = (const float*)d_in[5];
    const float* att_d  = (const float*)d_in[6];
    const float* b_gat  = (const float*)d_in[7];
    const float* W2     = (const float*)d_in[8];
    const float* b2     = (const float*)d_in[9];
    const float* W3     = (const float*)d_in[10];
    const float* b3     = (const float*)d_in[11];
    const float* c1w    = (const float*)d_in[12];
    const float* c1b    = (const float*)d_in[13];
    const float* c2w    = (const float*)d_in[14];
    const float* c2b    = (const float*)d_in[15];
    const float* bn1g   = (const float*)d_in[16];
    const float* bn1b   = (const float*)d_in[17];
    const float* bn1m   = (const float*)d_in[18];
    const float* bn1v   = (const float*)d_in[19];
    const float* bn2g   = (const float*)d_in[20];
    const float* bn2b   = (const float*)d_in[21];
    const float* bn2m   = (const float*)d_in[22];
    const float* bn2v   = (const float*)d_in[23];
    const float* fc1W   = (const float*)d_in[24];
    const float* fc1b   = (const float*)d_in[25];
    const float* fusW   = (const float*)d_in[26];
    const float* fusb   = (const float*)d_in[27];
    const float* cl1W   = (const float*)d_in[28];
    const float* cl1b   = (const float*)d_in[29];
    const float* cl3W   = (const float*)d_in[30];
    const float* cl3b   = (const float*)d_in[31];
    float* out = (float*)d_out;

    int n = in_sizes[0] / 9;
    int E = in_sizes[1] / 2;
    int b = in_sizes[3] / (CH * SEQL);
    if (n > MAXN || E > MAXE || b > BSZ) return;

    // sequence branch + GAT node transform + pool init (single stream)
    k_conv1<<<512, 256>>>(seq, c1w, c1b, bn1g, bn1b, bn1m, bn1v, b);
    k_conv2<<<512, 256>>>(c2w, c2b, bn2g, bn2b, bn2m, bn2v, b);
    k_fc1g<<<(b + 63) / 64, 256>>>(fc1W, fc1b, b);
    k_gat_node<<<(n + 15) / 16, 128>>>(x, W_gat, att_s, att_d, n);
    k_zero_pool<<<(b * 128 + 255) / 256, 256>>>(b);
    k_cntb<<<(n + 255) / 256, 256>>>(batch, n);

    // CSR build
    k_deg_init<<<(n + 255) / 256, 256>>>(n);
    k_count<<<2048, 256>>>(ei, E);
    int NB = (n + 511) / 512;
    k_scan1<<<NB, 512>>>(n);
    k_scan2<<<1, 512>>>(NB);
    k_scan3<<<NB, 512>>>(n, E + n);
    k_selfloop<<<(n + 255) / 256, 256>>>(n);
    k_scatter<<<2048, 256>>>(ei, E);

    // GAT aggregate -> g1
    k_gat_agg<<<(n + 7) / 8, 256>>>(b_gat, n);

    // GCN layer 2: h2 = g1@W2 ; g2 = lrelu(A@h2 + b2)
    k_mm1<<<592, 256>>>(W2, n);
    k_agg64_act<<<(n + 7) / 8, 256>>>(b2, n);

    // GCN layer 3 (linearity): agg = A@g2 (64-dim), then
    // per-node out = lrelu(agg@W3 + b3) accumulated straight into the pool
    k_agg64_plain<<<(n + 7) / 8, 256>>>(n);
    k_mm3pool<<<592, 256>>>(W3, b3, batch, n);
    k_pool_div<<<(b * 128 + 255) / 256, 256>>>(b);

    // fusion + classifier
    k_head<<<(b + 3) / 4, 128>>>(fusW, fusb, cl1W, cl1b, cl3W, cl3b, out, b);
}

// round 14
// speedup vs baseline: 1.3471x; 1.0732x over previous
#include <cuda_runtime.h>
#include <cuda_fp16.h>
#include <math.h>
#include <stdint.h>

// Problem constants (fixed by the dataset)
#define MAXN 100000
#define MAXE 1600000
#define MAXT (MAXN + MAXE)
#define BSZ  1024
#define CH   30
#define SEQL 20

// ---------------- scratch (static device globals; no allocation) -------------
__device__ __half d_h[(size_t)MAXN * 128];   // GAT h (fp16)
__device__ __half d_g1[(size_t)MAXN * 128];  // GAT out g1 (fp16)
__device__ __half d_h2[(size_t)MAXN * 64];   // h2 = g1@W2 (fp16)
__device__ __half d_g2[(size_t)MAXN * 64];   // g2 (fp16)
__device__ __half d_agg[(size_t)MAXN * 64];  // A@g2 (fp16)
__device__ float d_as[MAXN * 4];
__device__ float d_ad[MAXN * 4];
__device__ int   d_deg[MAXN];
__device__ int   d_rowptr[MAXN + 1];
__device__ int   d_cursor[MAXN];
__device__ int   d_col[MAXT];
__device__ int   d_bsums[1024];
__device__ float d_dinv[MAXN];
__device__ float d_pool[BSZ * 128];
__device__ float d_cntb[BSZ];
__device__ float d_s1[BSZ * 64 * 18];
__device__ float d_s2[BSZ * 64 * 16];
__device__ float d_sfc[BSZ * 64];

__device__ __forceinline__ float lrelu(float x, float s) { return x >= 0.f ? x : s * x; }
__device__ __forceinline__ float warpSum(float v) {
#pragma unroll
    for (int o = 16; o > 0; o >>= 1) v += __shfl_xor_sync(0xffffffffu, v, o);
    return v;
}
__device__ __forceinline__ float sum8(float v) {
#pragma unroll
    for (int o = 4; o > 0; o >>= 1) v += __shfl_xor_sync(0xffffffffu, v, o);
    return v;
}
__device__ __forceinline__ void sth4(__half* p, float4 v) {
    __half2 a = __floats2half2_rn(v.x, v.y);
    __half2 b = __floats2half2_rn(v.z, v.w);
    uint2 u;
    u.x = *reinterpret_cast<unsigned*>(&a);
    u.y = *reinterpret_cast<unsigned*>(&b);
    *(uint2*)p = u;
}

// ---------------- K1: h = x @ W_gat ; a_s, a_d ------------------------------
__global__ void k_gat_node(const float* __restrict__ x, const float* __restrict__ Wg,
                           const float* __restrict__ asrc, const float* __restrict__ adst, int n) {
    int lane = threadIdx.x & 31;   // column group: channels 4*lane .. 4*lane+3
    int wid  = threadIdx.x >> 5;   // node-lane 0..3
    float w[9][4];
#pragma unroll
    for (int f = 0; f < 9; f++)
#pragma unroll
        for (int q = 0; q < 4; q++) w[f][q] = Wg[f * 128 + 4 * lane + q];
    float atts[4], attd[4];
#pragma unroll
    for (int q = 0; q < 4; q++) { atts[q] = asrc[4 * lane + q]; attd[q] = adst[4 * lane + q]; }
    __shared__ float sx[16 * 9];
    int base = blockIdx.x * 16;
    int cnt = min(16, n - base);
    if (cnt <= 0) return;
    for (int i = threadIdx.x; i < cnt * 9; i += 128) sx[i] = x[base * 9 + i];
    __syncthreads();
    int hh = lane >> 3;  // head
#pragma unroll
    for (int t = 0; t < 4; t++) {
        int li = t * 4 + wid;
        int node = base + li;
        if (li >= cnt) break;
        float h[4] = {0.f, 0.f, 0.f, 0.f};
#pragma unroll
        for (int f = 0; f < 9; f++) {
            float xv = sx[li * 9 + f];
#pragma unroll
            for (int q = 0; q < 4; q++) h[q] += xv * w[f][q];
        }
        float ps = h[0] * atts[0] + h[1] * atts[1] + h[2] * atts[2] + h[3] * atts[3];
        float pd = h[0] * attd[0] + h[1] * attd[1] + h[2] * attd[2] + h[3] * attd[3];
        ps = sum8(ps); pd = sum8(pd);
        if ((lane & 7) == 0) {
            d_as[node * 4 + hh] = ps;
            d_ad[node * 4 + hh] = pd;
        }
        sth4(d_h + (size_t)node * 128 + 4 * lane, make_float4(h[0], h[1], h[2], h[3]));
    }
}

// ---------------- merged init: pool zero + cntb zero + deg init --------------
__global__ void k_init(int n, int b) {
    int i = blockIdx.x * blockDim.x + threadIdx.x;
    if (i < b * 128) d_pool[i] = 0.f;
    if (i < b) d_cntb[i] = 0.f;
    if (i < n) d_deg[i] = 1;  // self loop
}
__global__ void k_cntb(const int* __restrict__ batch, int n) {
    int i = blockIdx.x * blockDim.x + threadIdx.x;
    if (i < n) atomicAdd(&d_cntb[batch[i]], 1.f);
}

// ---------------- CSR build --------------------------------------------------
__global__ void k_count(const int* __restrict__ ei, int E) {
    for (int e = blockIdx.x * blockDim.x + threadIdx.x; e < E; e += gridDim.x * blockDim.x)
        atomicAdd(&d_deg[ei[E + e]], 1);
}
__global__ void k_scan1(int n) {
    __shared__ int ss[512];
    int idx = blockIdx.x * 512 + threadIdx.x;
    int val = (idx < n) ? d_deg[idx] : 0;
    ss[threadIdx.x] = val;
    __syncthreads();
#pragma unroll
    for (int off = 1; off < 512; off <<= 1) {
        int t = (threadIdx.x >= off) ? ss[threadIdx.x - off] : 0;
        __syncthreads();
        ss[threadIdx.x] += t;
        __syncthreads();
    }
    if (idx < n) d_rowptr[idx] = ss[threadIdx.x] - val;  // exclusive
    if (threadIdx.x == 511) d_bsums[blockIdx.x] = ss[511];
}
__global__ void k_scan2(int nb) {
    __shared__ int ss[512];
    int v = (threadIdx.x < nb) ? d_bsums[threadIdx.x] : 0;
    ss[threadIdx.x] = v;
    __syncthreads();
#pragma unroll
    for (int off = 1; off < 512; off <<= 1) {
        int t = (threadIdx.x >= off) ? ss[threadIdx.x - off] : 0;
        __syncthreads();
        ss[threadIdx.x] += t;
        __syncthreads();
    }
    if (threadIdx.x < nb) d_bsums[threadIdx.x] = ss[threadIdx.x] - v;  // exclusive
}
__global__ void k_scan3(int n, int tot) {
    int idx = blockIdx.x * 512 + threadIdx.x;
    if (idx < n) d_rowptr[idx] += d_bsums[blockIdx.x];
    if (idx == 0) d_rowptr[n] = tot;
}
__global__ void k_selfloop(int n) {
    int i = blockIdx.x * blockDim.x + threadIdx.x;
    if (i < n) {
        int p = d_rowptr[i];
        d_col[p] = i;
        d_cursor[i] = p + 1;
        d_dinv[i] = rsqrtf((float)d_deg[i]);
    }
}
__global__ void k_scatter(const int* __restrict__ ei, int E) {
    for (int e = blockIdx.x * blockDim.x + threadIdx.x; e < E; e += gridDim.x * blockDim.x) {
        int s = ei[e], d = ei[E + e];
        int pos = atomicAdd(&d_cursor[d], 1);
        d_col[pos] = s;
    }
}

// ---- GAT aggregate: ONE pass, no max-shift, 2 edges per warp-iteration ------
// warp = dst node. half-warp h (lanes 16h..16h+15) takes edge jb+h.
// lane sub (0..15) owns channels 8*sub..8*sub+7 (16B of the fp16 row).
__global__ void k_gat_agg(const float* __restrict__ bias, int n) {
    int warp = (blockIdx.x * blockDim.x + threadIdx.x) >> 5;
    int lane = threadIdx.x & 31;
    if (warp >= n) return;
    int i = warp;
    int start = d_rowptr[i], end = d_rowptr[i + 1];
    int half = lane >> 4;
    int sub  = lane & 15;
    int head = sub >> 2;            // 8 channels/lane, 32/head -> 4 lanes per head
    float4 ad4 = *(const float4*)(d_ad + 4 * i);
    float aad = head < 2 ? (head == 0 ? ad4.x : ad4.y) : (head == 2 ? ad4.z : ad4.w);
    float acc[8] = {0.f, 0.f, 0.f, 0.f, 0.f, 0.f, 0.f, 0.f};
    float ssum = 0.f;
    for (int jb = start; jb < end; jb += 2) {
        int j = jb + half;
        if (j < end) {
            int s = d_col[j];
            float4 a = *(const float4*)(d_as + 4 * s);
            float av = head < 2 ? (head == 0 ? a.x : a.y) : (head == 2 ? a.z : a.w);
            float w = __expf(lrelu(av + aad, 0.2f));
            ssum += w;
            uint4 u = *(const uint4*)(d_h + (size_t)s * 128 + 8 * sub);
            const __half2* hp = (const __half2*)&u;
#pragma unroll
            for (int q = 0; q < 4; q++) {
                float2 f = __half22float2(hp[q]);
                acc[2 * q]     += w * f.x;
                acc[2 * q + 1] += w * f.y;
            }
        }
    }
#pragma unroll
    for (int q = 0; q < 8; q++) acc[q] += __shfl_xor_sync(0xffffffffu, acc[q], 16);
    ssum += __shfl_xor_sync(0xffffffffu, ssum, 16);
    if (half == 0) {
        float inv = 1.f / (ssum + 1e-16f);
        const float4* bp = (const float4*)(bias + 8 * sub);
        float4 b0 = bp[0], b1 = bp[1];
        float o0 = lrelu(acc[0] * inv + b0.x, 0.01f);
        float o1 = lrelu(acc[1] * inv + b0.y, 0.01f);
        float o2 = lrelu(acc[2] * inv + b0.z, 0.01f);
        float o3 = lrelu(acc[3] * inv + b0.w, 0.01f);
        float o4 = lrelu(acc[4] * inv + b1.x, 0.01f);
        float o5 = lrelu(acc[5] * inv + b1.y, 0.01f);
        float o6 = lrelu(acc[6] * inv + b1.z, 0.01f);
        float o7 = lrelu(acc[7] * inv + b1.w, 0.01f);
        __half2 p0 = __floats2half2_rn(o0, o1);
        __half2 p1 = __floats2half2_rn(o2, o3);
        __half2 p2 = __floats2half2_rn(o4, o5);
        __half2 p3 = __floats2half2_rn(o6, o7);
        uint4 u;
        u.x = *reinterpret_cast<unsigned*>(&p0);
        u.y = *reinterpret_cast<unsigned*>(&p1);
        u.z = *reinterpret_cast<unsigned*>(&p2);
        u.w = *reinterpret_cast<unsigned*>(&p3);
        *(uint4*)(d_g1 + (size_t)i * 128 + 8 * sub) = u;
    }
}

// ---------------- h2 = g1[N,128] @ W2[128,64]  (register-tiled) --------------
__global__ void k_mm1(const float* __restrict__ W, int n) {
    __shared__ float sW[128 * 64];
    __shared__ float sX[64 * 128];
    const float4* W4 = (const float4*)W;
    float4* sW4 = (float4*)sW;
    for (int i = threadIdx.x; i < 128 * 64 / 4; i += 256) sW4[i] = W4[i];
    int cg = threadIdx.x & 15, ng = threadIdx.x >> 4;
    for (int base = blockIdx.x * 64; base < n; base += gridDim.x * 64) {
        __syncthreads();
        int cnt = min(64, n - base);
        {
            const uint4* src = (const uint4*)(d_g1 + (size_t)base * 128);
            float4* dst = (float4*)sX;
            int tot = cnt * 16;  // uint4 = 8 halves
            for (int i = threadIdx.x; i < tot; i += 256) {
                uint4 u = src[i];
                const __half2* hp = (const __half2*)&u;
                float2 f0 = __half22float2(hp[0]), f1 = __half22float2(hp[1]);
                float2 f2 = __half22float2(hp[2]), f3 = __half22float2(hp[3]);
                dst[2 * i]     = make_float4(f0.x, f0.y, f1.x, f1.y);
                dst[2 * i + 1] = make_float4(f2.x, f2.y, f3.x, f3.y);
            }
        }
        __syncthreads();
        float acc[4][4];
#pragma unroll
        for (int i = 0; i < 4; i++)
#pragma unroll
            for (int q = 0; q < 4; q++) acc[i][q] = 0.f;
        const float4* sWc = (const float4*)sW;
#pragma unroll 4
        for (int k = 0; k < 128; k++) {
            float4 w4 = sWc[k * 16 + cg];
#pragma unroll
            for (int i = 0; i < 4; i++) {
                float xv = sX[(ng * 4 + i) * 128 + k];
                acc[i][0] += xv * w4.x; acc[i][1] += xv * w4.y;
                acc[i][2] += xv * w4.z; acc[i][3] += xv * w4.w;
            }
        }
#pragma unroll
        for (int i = 0; i < 4; i++) {
            int node = base + ng * 4 + i;
            if (node < n)
                sth4(d_h2 + (size_t)node * 64 + cg * 4,
                     make_float4(acc[i][0], acc[i][1], acc[i][2], acc[i][3]));
        }
    }
}

// ------ 64-dim GCN aggregation: 2 edges per warp-iteration (fp16 rows) -------
// lane sub (0..15) owns channels 4*sub..4*sub+3 (8B of the fp16 row).
__device__ __forceinline__ void agg64_2e(const __half* __restrict__ in, __half* __restrict__ outp,
                                         const float* __restrict__ bias, int n, bool act) {
    int warp = (blockIdx.x * blockDim.x + threadIdx.x) >> 5;
    int lane = threadIdx.x & 31;
    if (warp >= n) return;
    int i = warp;
    int start = d_rowptr[i], end = d_rowptr[i + 1];
    int half = lane >> 4;
    int sub  = lane & 15;
    float dvi = d_dinv[i];
    float a0 = 0.f, a1 = 0.f, a2 = 0.f, a3 = 0.f;
    for (int jb = start; jb < end; jb += 2) {
        int j = jb + half;
        if (j < end) {
            int s = d_col[j];
            float w = d_dinv[s];
            uint2 u = *(const uint2*)(in + (size_t)s * 64 + 4 * sub);
            float2 f0 = __half22float2(*reinterpret_cast<const __half2*>(&u.x));
            float2 f1 = __half22float2(*reinterpret_cast<const __half2*>(&u.y));
            a0 += w * f0.x; a1 += w * f0.y; a2 += w * f1.x; a3 += w * f1.y;
        }
    }
    a0 += __shfl_xor_sync(0xffffffffu, a0, 16);
    a1 += __shfl_xor_sync(0xffffffffu, a1, 16);
    a2 += __shfl_xor_sync(0xffffffffu, a2, 16);
    a3 += __shfl_xor_sync(0xffffffffu, a3, 16);
    if (half == 0) {
        a0 *= dvi; a1 *= dvi; a2 *= dvi; a3 *= dvi;
        if (act) {
            float4 b4 = *(const float4*)(bias + 4 * sub);
            a0 = lrelu(a0 + b4.x, 0.01f);
            a1 = lrelu(a1 + b4.y, 0.01f);
            a2 = lrelu(a2 + b4.z, 0.01f);
            a3 = lrelu(a3 + b4.w, 0.01f);
        }
        sth4(outp + (size_t)i * 64 + 4 * sub, make_float4(a0, a1, a2, a3));
    }
}
__global__ void k_agg64_act(const float* __restrict__ bias, int n) {
    agg64_2e(d_h2, d_g2, bias, n, true);     // g2 = lrelu(A@h2 + b2)
}
__global__ void k_agg64_plain(int n) {
    agg64_2e(d_g2, d_agg, nullptr, n, false); // agg = A@g2
}

// ------- layer-3 matmul (64->128) + bias + lrelu + pool (register-tiled) -----
__global__ void k_mm3pool(const float* __restrict__ W, const float* __restrict__ bias,
                          const int* __restrict__ batch, int n) {
    __shared__ float sW[64 * 128];
    __shared__ float sX[64 * 64];
    __shared__ float sb[128];
    __shared__ int sbt[64];
    const float4* W4 = (const float4*)W;
    float4* sW4 = (float4*)sW;
    for (int i = threadIdx.x; i < 64 * 128 / 4; i += 256) sW4[i] = W4[i];
    if (threadIdx.x < 128) sb[threadIdx.x] = bias[threadIdx.x];
    int cg = threadIdx.x & 31, ng = threadIdx.x >> 5;
    for (int base = blockIdx.x * 64; base < n; base += gridDim.x * 64) {
        __syncthreads();
        int cnt = min(64, n - base);
        {
            const uint4* src = (const uint4*)(d_agg + (size_t)base * 64);
            float4* dst = (float4*)sX;
            int tot = cnt * 8;  // uint4 = 8 halves
            for (int i = threadIdx.x; i < tot; i += 256) {
                uint4 u = src[i];
                const __half2* hp = (const __half2*)&u;
                float2 f0 = __half22float2(hp[0]), f1 = __half22float2(hp[1]);
                float2 f2 = __half22float2(hp[2]), f3 = __half22float2(hp[3]);
                dst[2 * i]     = make_float4(f0.x, f0.y, f1.x, f1.y);
                dst[2 * i + 1] = make_float4(f2.x, f2.y, f3.x, f3.y);
            }
        }
        if (threadIdx.x < 64 && threadIdx.x < cnt) sbt[threadIdx.x] = batch[base + threadIdx.x];
        __syncthreads();
        float acc[8][4];
#pragma unroll
        for (int i = 0; i < 8; i++)
#pragma unroll
            for (int q = 0; q < 4; q++) acc[i][q] = 0.f;
        const float4* sWc = (const float4*)sW;
#pragma unroll 4
        for (int k = 0; k < 64; k++) {
            float4 w4 = sWc[k * 32 + cg];
#pragma unroll
            for (int i = 0; i < 8; i++) {
                float xv = sX[(ng * 8 + i) * 64 + k];
                acc[i][0] += xv * w4.x; acc[i][1] += xv * w4.y;
                acc[i][2] += xv * w4.z; acc[i][3] += xv * w4.w;
            }
        }
        float b0 = sb[cg * 4 + 0], b1 = sb[cg * 4 + 1], b2v = sb[cg * 4 + 2], b3v = sb[cg * 4 + 3];
#pragma unroll
        for (int i = 0; i < 8; i++) {
            int li = ng * 8 + i;
            int node = base + li;
            if (node < n) {
                float* pp = d_pool + (size_t)sbt[li] * 128 + cg * 4;
                atomicAdd(pp + 0, lrelu(acc[i][0] + b0, 0.01f));
                atomicAdd(pp + 1, lrelu(acc[i][1] + b1, 0.01f));
                atomicAdd(pp + 2, lrelu(acc[i][2] + b2v, 0.01f));
                atomicAdd(pp + 3, lrelu(acc[i][3] + b3v, 0.01f));
            }
        }
    }
}

__global__ void k_pool_div(int b) {
    int i = blockIdx.x * blockDim.x + threadIdx.x;
    if (i < b * 128) d_pool[i] /= fmaxf(d_cntb[i >> 7], 1.f);
}

// ---------------- sequence branch -------------------------------------------
__global__ void k_conv1(const float* __restrict__ seq, const float* __restrict__ w,
                        const float* __restrict__ bconv,
                        const float* __restrict__ g, const float* __restrict__ be,
                        const float* __restrict__ m, const float* __restrict__ v, int b) {
    __shared__ float sw[64 * 30 * 3];
    for (int i = threadIdx.x; i < 64 * 30 * 3; i += 256) sw[i] = w[i];
    __syncthreads();
    int total = b * 64 * 18;
    for (int idx = blockIdx.x * blockDim.x + threadIdx.x; idx < total; idx += gridDim.x * blockDim.x) {
        int pos = idx % 18, co = (idx / 18) % 64, bb = idx / (18 * 64);
        float acc = bconv[co];
        const float* xb = seq + bb * (CH * SEQL);
        const float* wp = sw + co * 90;
#pragma unroll
        for (int cin = 0; cin < 30; cin++) {
            const float* xp = xb + cin * 20 + pos;
            acc += xp[0] * wp[cin * 3 + 0] + xp[1] * wp[cin * 3 + 1] + xp[2] * wp[cin * 3 + 2];
        }
        float sc = g[co] * rsqrtf(v[co] + 1e-5f);
        float sh = be[co] - m[co] * sc;
        d_s1[idx] = lrelu(acc * sc + sh, 0.01f);
    }
}
__global__ void k_conv2(const float* __restrict__ w, const float* __restrict__ bconv,
                        const float* __restrict__ g, const float* __restrict__ be,
                        const float* __restrict__ m, const float* __restrict__ v, int b) {
    __shared__ float sw[64 * 64 * 3];  // 48KB
    for (int i = threadIdx.x; i < 64 * 64 * 3; i += 256) sw[i] = w[i];
    __syncthreads();
    int total = b * 64 * 16;
    for (int idx = blockIdx.x * blockDim.x + threadIdx.x; idx < total; idx += gridDim.x * blockDim.x) {
        int pos = idx % 16, co = (idx / 16) % 64, bb = idx / (16 * 64);
        float acc = bconv[co];
        const float* xb = d_s1 + bb * (64 * 18);
        const float* wp = sw + co * 192;
#pragma unroll 8
        for (int cin = 0; cin < 64; cin++) {
            const float* xp = xb + cin * 18 + pos;
            acc += xp[0] * wp[cin * 3 + 0] + xp[1] * wp[cin * 3 + 1] + xp[2] * wp[cin * 3 + 2];
        }
        float sc = g[co] * rsqrtf(v[co] + 1e-5f);
        float sh = be[co] - m[co] * sc;
        d_s2[idx] = lrelu(acc * sc + sh, 0.01f);
    }
}

// fc1 as a tiled GEMM: [B,1024] @ [1024,64]  (64 rows per block)
__global__ void k_fc1g(const float* __restrict__ W, const float* __restrict__ bias, int b) {
    __shared__ float sX[64][65];
    __shared__ float sW[64][64];
    int c = threadIdx.x & 63, rg = threadIdx.x >> 6;  // rg in [0,4)
    int rowbase = blockIdx.x * 64;
    float acc[16];
#pragma unroll
    for (int r = 0; r < 16; r++) acc[r] = 0.f;
    for (int kt = 0; kt < 16; kt++) {
        __syncthreads();
        for (int i = threadIdx.x; i < 64 * 64; i += 256) {
            int r = i >> 6, k = i & 63;
            int row = rowbase + r;
            sX[r][k] = (row < b) ? d_s2[row * 1024 + kt * 64 + k] : 0.f;
        }
        for (int i = threadIdx.x; i < 64 * 64; i += 256) {
            int k = i >> 6, cc = i & 63;
            sW[k][cc] = W[(kt * 64 + k) * 64 + cc];
        }
        __syncthreads();
#pragma unroll
        for (int k = 0; k < 64; k++) {
            float w = sW[k][c];
#pragma unroll
            for (int r = 0; r < 16; r++) acc[r] += sX[rg * 16 + r][k] * w;
        }
    }
    float bb = bias[c];
#pragma unroll
    for (int r = 0; r < 16; r++) {
        int row = rowbase + rg * 16 + r;
        if (row < b) d_sfc[row * 64 + c] = acc[r] + bb;
    }
}

// ---------------- fusion + classifier (4 graphs per block) -------------------
__global__ void k_head(const float* __restrict__ fusW, const float* __restrict__ fusb,
                       const float* __restrict__ c1W, const float* __restrict__ c1b,
                       const float* __restrict__ c3W, const float* __restrict__ c3b,
                       float* __restrict__ out, int b) {
    __shared__ float comb[4][192];
    __shared__ float t1[4][128];
    __shared__ float red[4][2];
    int tid = threadIdx.x;
    int b0 = blockIdx.x * 4;
    int nb = min(4, b - b0);
#pragma unroll
    for (int g = 0; g < 4; g++) {
        if (g < nb) {
            comb[g][tid] = d_pool[(b0 + g) * 128 + tid];
            if (tid < 64) comb[g][128 + tid] = d_sfc[(b0 + g) * 64 + tid];
        }
    }
    __syncthreads();
    float a0 = fusb[tid], a1 = a0, a2 = a0, a3 = a0;
    for (int k = 0; k < 192; k++) {
        float w = fusW[k * 128 + tid];
        a0 += comb[0][k] * w; a1 += comb[1][k] * w;
        a2 += comb[2][k] * w; a3 += comb[3][k] * w;
    }
    t1[0][tid] = lrelu(a0, 0.01f); t1[1][tid] = lrelu(a1, 0.01f);
    t1[2][tid] = lrelu(a2, 0.01f); t1[3][tid] = lrelu(a3, 0.01f);
    __syncthreads();
    if (tid < 64) {
        float q0 = c1b[tid], q1 = q0, q2 = q0, q3 = q0;
        for (int k = 0; k < 128; k++) {
            float w = c1W[k * 64 + tid];
            q0 += t1[0][k] * w; q1 += t1[1][k] * w;
            q2 += t1[2][k] * w; q3 += t1[3][k] * w;
        }
        float wc = c3W[tid];
        float v0 = lrelu(q0, 0.01f) * wc;
        float v1 = lrelu(q1, 0.01f) * wc;
        float v2 = lrelu(q2, 0.01f) * wc;
        float v3 = lrelu(q3, 0.01f) * wc;
        v0 = warpSum(v0); v1 = warpSum(v1); v2 = warpSum(v2); v3 = warpSum(v3);
        if ((tid & 31) == 0) {
            int h = tid >> 5;
            red[0][h] = v0; red[1][h] = v1; red[2][h] = v2; red[3][h] = v3;
        }
    }
    __syncthreads();
    if (tid < 4 && tid < nb) out[b0 + tid] = red[tid][0] + red[tid][1] + c3b[0];
}

// ---------------- launch ------------------------------------------------------
extern "C" void kernel_launch(void* const* d_in, const int* in_sizes, int n_in,
                              void* d_out, int out_size) {
    const float* x      = (const float*)d_in[0];
    const int*   ei     = (const int*)d_in[1];
    const int*   batch  = (const int*)d_in[2];
    const float* seq    = (const float*)d_in[3];
    const float* W_gat  = (const float*)d_in[4];
    const float* att_s  = (const float*)d_in[5];
    const float* att_d  = (const float*)d_in[6];
    const float* b_gat  = (const float*)d_in[7];
    const float* W2     = (const float*)d_in[8];
    const float* b2     = (const float*)d_in[9];
    const float* W3     = (const float*)d_in[10];
    const float* b3     = (const float*)d_in[11];
    const float* c1w    = (const float*)d_in[12];
    const float* c1b    = (const float*)d_in[13];
    const float* c2w    = (const float*)d_in[14];
    const float* c2b    = (const float*)d_in[15];
    const float* bn1g   = (const float*)d_in[16];
    const float* bn1b   = (const float*)d_in[17];
    const float* bn1m   = (const float*)d_in[18];
    const float* bn1v   = (const float*)d_in[19];
    const float* bn2g   = (const float*)d_in[20];
    const float* bn2b   = (const float*)d_in[21];
    const float* bn2m   = (const float*)d_in[22];
    const float* bn2v   = (const float*)d_in[23];
    const float* fc1W   = (const float*)d_in[24];
    const float* fc1b   = (const float*)d_in[25];
    const float* fusW   = (const float*)d_in[26];
    const float* fusb   = (const float*)d_in[27];
    const float* cl1W   = (const float*)d_in[28];
    const float* cl1b   = (const float*)d_in[29];
    const float* cl3W   = (const float*)d_in[30];
    const float* cl3b   = (const float*)d_in[31];
    float* out = (float*)d_out;

    int n = in_sizes[0] / 9;
    int E = in_sizes[1] / 2;
    int b = in_sizes[3] / (CH * SEQL);
    if (n > MAXN || E > MAXE || b > BSZ) return;

    // sequence branch + GAT node transform + init (single stream)
    k_conv1<<<512, 256>>>(seq, c1w, c1b, bn1g, bn1b, bn1m, bn1v, b);
    k_conv2<<<512, 256>>>(c2w, c2b, bn2g, bn2b, bn2m, bn2v, b);
    k_fc1g<<<(b + 63) / 64, 256>>>(fc1W, fc1b, b);
    k_gat_node<<<(n + 15) / 16, 128>>>(x, W_gat, att_s, att_d, n);
    int initN = (n > b * 128 ? n : b * 128);
    k_init<<<(initN + 255) / 256, 256>>>(n, b);
    k_cntb<<<(n + 255) / 256, 256>>>(batch, n);

    // CSR build
    k_count<<<2048, 256>>>(ei, E);
    int NB = (n + 511) / 512;
    k_scan1<<<NB, 512>>>(n);
    k_scan2<<<1, 512>>>(NB);
    k_scan3<<<NB, 512>>>(n, E + n);
    k_selfloop<<<(n + 255) / 256, 256>>>(n);
    k_scatter<<<2048, 256>>>(ei, E);

    // GAT aggregate -> g1 (single pass)
    k_gat_agg<<<(n + 7) / 8, 256>>>(b_gat, n);

    // GCN layer 2: h2 = g1@W2 ; g2 = lrelu(A@h2 + b2)
    k_mm1<<<592, 256>>>(W2, n);
    k_agg64_act<<<(n + 7) / 8, 256>>>(b2, n);

    // GCN layer 3 (linearity): agg = A@g2 (64-dim), then
    // per-node out = lrelu(agg@W3 + b3) accumulated straight into the pool
    k_agg64_plain<<<(n + 7) / 8, 256>>>(n);
    k_mm3pool<<<592, 256>>>(W3, b3, batch, n);
    k_pool_div<<<(b * 128 + 255) / 256, 256>>>(b);

    // fusion + classifier
    k_head<<<(b + 3) / 4, 128>>>(fusW, fusb, cl1W, cl1b, cl3W, cl3b, out, b);
}

// round 15
// speedup vs baseline: 1.3515x; 1.0033x over previous
#include <cuda_runtime.h>
#include <cuda_fp16.h>
#include <math.h>
#include <stdint.h>

// Problem constants (fixed by the dataset)
#define MAXN 100000
#define MAXE 1600000
#define MAXT (MAXN + MAXE)
#define BSZ  1024
#define CH   30
#define SEQL 20

// ---------------- scratch (static device globals; no allocation) -------------
__device__ __half d_h[(size_t)MAXN * 128];   // GAT h (fp16)
__device__ __half d_g1[(size_t)MAXN * 128];  // GAT out g1 (fp16)
__device__ __half d_h2[(size_t)MAXN * 64];   // h2 = g1@W2 (fp16)
__device__ __half d_g2[(size_t)MAXN * 64];   // g2 (fp16)
__device__ __half d_agg[(size_t)MAXN * 64];  // A@g2 (fp16)
__device__ float d_as[MAXN * 4];
__device__ float d_ad[MAXN * 4];
__device__ float d_was[36];  // W_gat @ att_src  [9][4]
__device__ float d_wad[36];  // W_gat @ att_dst  [9][4]
__device__ int   d_deg[MAXN];
__device__ int   d_rowptr[MAXN + 1];
__device__ int   d_cursor[MAXN];
__device__ int   d_col[MAXT];
__device__ int   d_bsums[1024];
__device__ float d_dinv[MAXN];
__device__ float d_pool[BSZ * 128];
__device__ float d_cntb[BSZ];
__device__ float d_s1[BSZ * 64 * 18];
__device__ float d_s2[BSZ * 64 * 16];
__device__ float d_sfc[BSZ * 64];

__device__ __forceinline__ float lrelu(float x, float s) { return x >= 0.f ? x : s * x; }
__device__ __forceinline__ float warpSum(float v) {
#pragma unroll
    for (int o = 16; o > 0; o >>= 1) v += __shfl_xor_sync(0xffffffffu, v, o);
    return v;
}
__device__ __forceinline__ void sth4(__half* p, float4 v) {
    __half2 a = __floats2half2_rn(v.x, v.y);
    __half2 b = __floats2half2_rn(v.z, v.w);
    uint2 u;
    u.x = *reinterpret_cast<unsigned*>(&a);
    u.y = *reinterpret_cast<unsigned*>(&b);
    *(uint2*)p = u;
}

// ---------------- K0: Wa = W_gat @ att (9x4 each, exact algebra) -------------
__global__ void k_att_pre(const float* __restrict__ Wg, const float* __restrict__ asrc,
                          const float* __restrict__ adst) {
    int tid = threadIdx.x;
    if (tid < 72) {
        int idx = tid % 36;
        int f = idx >> 2, hh = idx & 3;
        const float* att = (tid < 36) ? asrc : adst;
        float s = 0.f;
#pragma unroll
        for (int c = 0; c < 32; c++) s += Wg[f * 128 + hh * 32 + c] * att[hh * 32 + c];
        if (tid < 36) d_was[idx] = s; else d_wad[idx] = s;
    }
}

// ---------------- K1: h = x @ W_gat (fp16) ; a_s, a_d via precomputed Wa -----
__global__ void k_gat_node(const float* __restrict__ x, const float* __restrict__ Wg, int n) {
    int lane = threadIdx.x & 31;   // column group: channels 4*lane .. 4*lane+3
    int wid  = threadIdx.x >> 5;   // node-lane 0..3
    float w[9][4];
#pragma unroll
    for (int f = 0; f < 9; f++)
#pragma unroll
        for (int q = 0; q < 4; q++) w[f][q] = Wg[f * 128 + 4 * lane + q];
    __shared__ float sx[16 * 9];
    __shared__ float sWas[36], sWad[36];
    if (threadIdx.x < 36) sWas[threadIdx.x] = d_was[threadIdx.x];
    else if (threadIdx.x < 72) sWad[threadIdx.x - 36] = d_wad[threadIdx.x - 36];
    int base = blockIdx.x * 16;
    int cnt = min(16, n - base);
    if (cnt <= 0) return;
    for (int i = threadIdx.x; i < cnt * 9; i += 128) sx[i] = x[base * 9 + i];
    __syncthreads();
    // attention coefficients: 128 threads -> (li, hh, s/d), 9 FMA each
    {
        int li = threadIdx.x >> 3;
        int hh = (threadIdx.x >> 1) & 3;
        int sd = threadIdx.x & 1;
        if (li < cnt) {
            const float* wa = sd ? sWad : sWas;
            float s = 0.f;
#pragma unroll
            for (int f = 0; f < 9; f++) s += sx[li * 9 + f] * wa[f * 4 + hh];
            if (sd) d_ad[(base + li) * 4 + hh] = s;
            else    d_as[(base + li) * 4 + hh] = s;
        }
    }
    // h rows
#pragma unroll
    for (int t = 0; t < 4; t++) {
        int li = t * 4 + wid;
        int node = base + li;
        if (li >= cnt) break;
        float h[4] = {0.f, 0.f, 0.f, 0.f};
#pragma unroll
        for (int f = 0; f < 9; f++) {
            float xv = sx[li * 9 + f];
#pragma unroll
            for (int q = 0; q < 4; q++) h[q] += xv * w[f][q];
        }
        sth4(d_h + (size_t)node * 128 + 4 * lane, make_float4(h[0], h[1], h[2], h[3]));
    }
}

// ---------------- merged init: pool zero + cntb zero + deg init --------------
__global__ void k_init(int n, int b) {
    int i = blockIdx.x * blockDim.x + threadIdx.x;
    if (i < b * 128) d_pool[i] = 0.f;
    if (i < b) d_cntb[i] = 0.f;
    if (i < n) d_deg[i] = 1;  // self loop
}
__global__ void k_cntb(const int* __restrict__ batch, int n) {
    int i = blockIdx.x * blockDim.x + threadIdx.x;
    if (i < n) atomicAdd(&d_cntb[batch[i]], 1.f);
}

// ---------------- CSR build --------------------------------------------------
__global__ void k_count(const int* __restrict__ ei, int E) {
    for (int e = blockIdx.x * blockDim.x + threadIdx.x; e < E; e += gridDim.x * blockDim.x)
        atomicAdd(&d_deg[ei[E + e]], 1);
}
__global__ void k_scan1(int n) {
    __shared__ int ss[512];
    int idx = blockIdx.x * 512 + threadIdx.x;
    int val = (idx < n) ? d_deg[idx] : 0;
    ss[threadIdx.x] = val;
    __syncthreads();
#pragma unroll
    for (int off = 1; off < 512; off <<= 1) {
        int t = (threadIdx.x >= off) ? ss[threadIdx.x - off] : 0;
        __syncthreads();
        ss[threadIdx.x] += t;
        __syncthreads();
    }
    if (idx < n) d_rowptr[idx] = ss[threadIdx.x] - val;  // exclusive
    if (threadIdx.x == 511) d_bsums[blockIdx.x] = ss[511];
}
__global__ void k_scan2(int nb) {
    __shared__ int ss[512];
    int v = (threadIdx.x < nb) ? d_bsums[threadIdx.x] : 0;
    ss[threadIdx.x] = v;
    __syncthreads();
#pragma unroll
    for (int off = 1; off < 512; off <<= 1) {
        int t = (threadIdx.x >= off) ? ss[threadIdx.x - off] : 0;
        __syncthreads();
        ss[threadIdx.x] += t;
        __syncthreads();
    }
    if (threadIdx.x < nb) d_bsums[threadIdx.x] = ss[threadIdx.x] - v;  // exclusive
}
// scan finalize + self-loop insert + cursor init + dinv (merged)
__global__ void k_scan3(int n, int tot) {
    int idx = blockIdx.x * 512 + threadIdx.x;
    if (idx < n) {
        int rp = d_rowptr[idx] + d_bsums[blockIdx.x];
        d_rowptr[idx] = rp;
        d_col[rp] = idx;          // self loop first
        d_cursor[idx] = rp + 1;
        d_dinv[idx] = rsqrtf((float)d_deg[idx]);
    }
    if (idx == 0) d_rowptr[n] = tot;
}
__global__ void k_scatter(const int* __restrict__ ei, int E) {
    for (int e = blockIdx.x * blockDim.x + threadIdx.x; e < E; e += gridDim.x * blockDim.x) {
        int s = ei[e], d = ei[E + e];
        int pos = atomicAdd(&d_cursor[d], 1);
        d_col[pos] = s;
    }
}

// ---- GAT aggregate: ONE pass, 4 edges in flight per warp-iteration ----------
// warp = dst node. half-warp h takes edges jb+h and jb+2+h.
// lane sub (0..15) owns channels 8*sub..8*sub+7 (16B of the fp16 row).
__global__ void k_gat_agg(const float* __restrict__ bias, int n) {
    int warp = (blockIdx.x * blockDim.x + threadIdx.x) >> 5;
    int lane = threadIdx.x & 31;
    if (warp >= n) return;
    int i = warp;
    int start = d_rowptr[i], end = d_rowptr[i + 1];
    int half = lane >> 4;
    int sub  = lane & 15;
    int head = sub >> 2;
    float4 ad4 = *(const float4*)(d_ad + 4 * i);
    float aad = head < 2 ? (head == 0 ? ad4.x : ad4.y) : (head == 2 ? ad4.z : ad4.w);
    float acc[8] = {0.f, 0.f, 0.f, 0.f, 0.f, 0.f, 0.f, 0.f};
    float ssum = 0.f;
    int jb = start;
    for (; jb + 4 <= end; jb += 4) {
        int j0 = jb + half, j1 = jb + 2 + half;
        int s0 = d_col[j0], s1 = d_col[j1];
        float4 a0 = *(const float4*)(d_as + 4 * s0);
        float4 a1 = *(const float4*)(d_as + 4 * s1);
        uint4 u0 = *(const uint4*)(d_h + (size_t)s0 * 128 + 8 * sub);
        uint4 u1 = *(const uint4*)(d_h + (size_t)s1 * 128 + 8 * sub);
        float av0 = head < 2 ? (head == 0 ? a0.x : a0.y) : (head == 2 ? a0.z : a0.w);
        float av1 = head < 2 ? (head == 0 ? a1.x : a1.y) : (head == 2 ? a1.z : a1.w);
        float w0 = __expf(lrelu(av0 + aad, 0.2f));
        float w1 = __expf(lrelu(av1 + aad, 0.2f));
        ssum += w0 + w1;
        const __half2* hp0 = (const __half2*)&u0;
        const __half2* hp1 = (const __half2*)&u1;
#pragma unroll
        for (int q = 0; q < 4; q++) {
            float2 f0 = __half22float2(hp0[q]);
            float2 f1 = __half22float2(hp1[q]);
            acc[2 * q]     += w0 * f0.x + w1 * f1.x;
            acc[2 * q + 1] += w0 * f0.y + w1 * f1.y;
        }
    }
    for (; jb < end; jb += 2) {
        int j = jb + half;
        if (j < end) {
            int s = d_col[j];
            float4 a = *(const float4*)(d_as + 4 * s);
            float av = head < 2 ? (head == 0 ? a.x : a.y) : (head == 2 ? a.z : a.w);
            float w = __expf(lrelu(av + aad, 0.2f));
            ssum += w;
            uint4 u = *(const uint4*)(d_h + (size_t)s * 128 + 8 * sub);
            const __half2* hp = (const __half2*)&u;
#pragma unroll
            for (int q = 0; q < 4; q++) {
                float2 f = __half22float2(hp[q]);
                acc[2 * q]     += w * f.x;
                acc[2 * q + 1] += w * f.y;
            }
        }
    }
#pragma unroll
    for (int q = 0; q < 8; q++) acc[q] += __shfl_xor_sync(0xffffffffu, acc[q], 16);
    ssum += __shfl_xor_sync(0xffffffffu, ssum, 16);
    if (half == 0) {
        float inv = 1.f / (ssum + 1e-16f);
        const float4* bp = (const float4*)(bias + 8 * sub);
        float4 b0 = bp[0], b1 = bp[1];
        float o0 = lrelu(acc[0] * inv + b0.x, 0.01f);
        float o1 = lrelu(acc[1] * inv + b0.y, 0.01f);
        float o2 = lrelu(acc[2] * inv + b0.z, 0.01f);
        float o3 = lrelu(acc[3] * inv + b0.w, 0.01f);
        float o4 = lrelu(acc[4] * inv + b1.x, 0.01f);
        float o5 = lrelu(acc[5] * inv + b1.y, 0.01f);
        float o6 = lrelu(acc[6] * inv + b1.z, 0.01f);
        float o7 = lrelu(acc[7] * inv + b1.w, 0.01f);
        __half2 p0 = __floats2half2_rn(o0, o1);
        __half2 p1 = __floats2half2_rn(o2, o3);
        __half2 p2 = __floats2half2_rn(o4, o5);
        __half2 p3 = __floats2half2_rn(o6, o7);
        uint4 u;
        u.x = *reinterpret_cast<unsigned*>(&p0);
        u.y = *reinterpret_cast<unsigned*>(&p1);
        u.z = *reinterpret_cast<unsigned*>(&p2);
        u.w = *reinterpret_cast<unsigned*>(&p3);
        *(uint4*)(d_g1 + (size_t)i * 128 + 8 * sub) = u;
    }
}

// ---------------- h2 = g1[N,128] @ W2[128,64]  (register-tiled) --------------
__global__ void k_mm1(const float* __restrict__ W, int n) {
    __shared__ float sW[128 * 64];
    __shared__ float sX[64 * 128];
    const float4* W4 = (const float4*)W;
    float4* sW4 = (float4*)sW;
    for (int i = threadIdx.x; i < 128 * 64 / 4; i += 256) sW4[i] = W4[i];
    int cg = threadIdx.x & 15, ng = threadIdx.x >> 4;
    for (int base = blockIdx.x * 64; base < n; base += gridDim.x * 64) {
        __syncthreads();
        int cnt = min(64, n - base);
        {
            const uint4* src = (const uint4*)(d_g1 + (size_t)base * 128);
            float4* dst = (float4*)sX;
            int tot = cnt * 16;  // uint4 = 8 halves
            for (int i = threadIdx.x; i < tot; i += 256) {
                uint4 u = src[i];
                const __half2* hp = (const __half2*)&u;
                float2 f0 = __half22float2(hp[0]), f1 = __half22float2(hp[1]);
                float2 f2 = __half22float2(hp[2]), f3 = __half22float2(hp[3]);
                dst[2 * i]     = make_float4(f0.x, f0.y, f1.x, f1.y);
                dst[2 * i + 1] = make_float4(f2.x, f2.y, f3.x, f3.y);
            }
        }
        __syncthreads();
        float acc[4][4];
#pragma unroll
        for (int i = 0; i < 4; i++)
#pragma unroll
            for (int q = 0; q < 4; q++) acc[i][q] = 0.f;
        const float4* sWc = (const float4*)sW;
#pragma unroll 4
        for (int k = 0; k < 128; k++) {
            float4 w4 = sWc[k * 16 + cg];
#pragma unroll
            for (int i = 0; i < 4; i++) {
                float xv = sX[(ng * 4 + i) * 128 + k];
                acc[i][0] += xv * w4.x; acc[i][1] += xv * w4.y;
                acc[i][2] += xv * w4.z; acc[i][3] += xv * w4.w;
            }
        }
#pragma unroll
        for (int i = 0; i < 4; i++) {
            int node = base + ng * 4 + i;
            if (node < n)
                sth4(d_h2 + (size_t)node * 64 + cg * 4,
                     make_float4(acc[i][0], acc[i][1], acc[i][2], acc[i][3]));
        }
    }
}

// ------ 64-dim GCN aggregation: 4 edges in flight (fp16 rows) ----------------
__device__ __forceinline__ void agg64_4e(const __half* __restrict__ in, __half* __restrict__ outp,
                                         const float* __restrict__ bias, int n, bool act) {
    int warp = (blockIdx.x * blockDim.x + threadIdx.x) >> 5;
    int lane = threadIdx.x & 31;
    if (warp >= n) return;
    int i = warp;
    int start = d_rowptr[i], end = d_rowptr[i + 1];
    int half = lane >> 4;
    int sub  = lane & 15;
    float dvi = d_dinv[i];
    float a0 = 0.f, a1 = 0.f, a2 = 0.f, a3 = 0.f;
    int jb = start;
    for (; jb + 4 <= end; jb += 4) {
        int j0 = jb + half, j1 = jb + 2 + half;
        int s0 = d_col[j0], s1 = d_col[j1];
        float w0 = d_dinv[s0], w1 = d_dinv[s1];
        uint2 u0 = *(const uint2*)(in + (size_t)s0 * 64 + 4 * sub);
        uint2 u1 = *(const uint2*)(in + (size_t)s1 * 64 + 4 * sub);
        float2 f00 = __half22float2(*reinterpret_cast<const __half2*>(&u0.x));
        float2 f01 = __half22float2(*reinterpret_cast<const __half2*>(&u0.y));
        float2 f10 = __half22float2(*reinterpret_cast<const __half2*>(&u1.x));
        float2 f11 = __half22float2(*reinterpret_cast<const __half2*>(&u1.y));
        a0 += w0 * f00.x + w1 * f10.x;
        a1 += w0 * f00.y + w1 * f10.y;
        a2 += w0 * f01.x + w1 * f11.x;
        a3 += w0 * f01.y + w1 * f11.y;
    }
    for (; jb < end; jb += 2) {
        int j = jb + half;
        if (j < end) {
            int s = d_col[j];
            float w = d_dinv[s];
            uint2 u = *(const uint2*)(in + (size_t)s * 64 + 4 * sub);
            float2 f0 = __half22float2(*reinterpret_cast<const __half2*>(&u.x));
            float2 f1 = __half22float2(*reinterpret_cast<const __half2*>(&u.y));
            a0 += w * f0.x; a1 += w * f0.y; a2 += w * f1.x; a3 += w * f1.y;
        }
    }
    a0 += __shfl_xor_sync(0xffffffffu, a0, 16);
    a1 += __shfl_xor_sync(0xffffffffu, a1, 16);
    a2 += __shfl_xor_sync(0xffffffffu, a2, 16);
    a3 += __shfl_xor_sync(0xffffffffu, a3, 16);
    if (half == 0) {
        a0 *= dvi; a1 *= dvi; a2 *= dvi; a3 *= dvi;
        if (act) {
            float4 b4 = *(const float4*)(bias + 4 * sub);
            a0 = lrelu(a0 + b4.x, 0.01f);
            a1 = lrelu(a1 + b4.y, 0.01f);
            a2 = lrelu(a2 + b4.z, 0.01f);
            a3 = lrelu(a3 + b4.w, 0.01f);
        }
        sth4(outp + (size_t)i * 64 + 4 * sub, make_float4(a0, a1, a2, a3));
    }
}
__global__ void k_agg64_act(const float* __restrict__ bias, int n) {
    agg64_4e(d_h2, d_g2, bias, n, true);     // g2 = lrelu(A@h2 + b2)
}
__global__ void k_agg64_plain(int n) {
    agg64_4e(d_g2, d_agg, nullptr, n, false); // agg = A@g2
}

// ------- layer-3 matmul (64->128) + bias + lrelu + pool (register-tiled) -----
__global__ void k_mm3pool(const float* __restrict__ W, const float* __restrict__ bias,
                          const int* __restrict__ batch, int n) {
    __shared__ float sW[64 * 128];
    __shared__ float sX[64 * 64];
    __shared__ float sb[128];
    __shared__ int sbt[64];
    const float4* W4 = (const float4*)W;
    float4* sW4 = (float4*)sW;
    for (int i = threadIdx.x; i < 64 * 128 / 4; i += 256) sW4[i] = W4[i];
    if (threadIdx.x < 128) sb[threadIdx.x] = bias[threadIdx.x];
    int cg = threadIdx.x & 31, ng = threadIdx.x >> 5;
    for (int base = blockIdx.x * 64; base < n; base += gridDim.x * 64) {
        __syncthreads();
        int cnt = min(64, n - base);
        {
            const uint4* src = (const uint4*)(d_agg + (size_t)base * 64);
            float4* dst = (float4*)sX;
            int tot = cnt * 8;  // uint4 = 8 halves
            for (int i = threadIdx.x; i < tot; i += 256) {
                uint4 u = src[i];
                const __half2* hp = (const __half2*)&u;
                float2 f0 = __half22float2(hp[0]), f1 = __half22float2(hp[1]);
                float2 f2 = __half22float2(hp[2]), f3 = __half22float2(hp[3]);
                dst[2 * i]     = make_float4(f0.x, f0.y, f1.x, f1.y);
                dst[2 * i + 1] = make_float4(f2.x, f2.y, f3.x, f3.y);
            }
        }
        if (threadIdx.x < 64 && threadIdx.x < cnt) sbt[threadIdx.x] = batch[base + threadIdx.x];
        __syncthreads();
        float acc[8][4];
#pragma unroll
        for (int i = 0; i < 8; i++)
#pragma unroll
            for (int q = 0; q < 4; q++) acc[i][q] = 0.f;
        const float4* sWc = (const float4*)sW;
#pragma unroll 4
        for (int k = 0; k < 64; k++) {
            float4 w4 = sWc[k * 32 + cg];
#pragma unroll
            for (int i = 0; i < 8; i++) {
                float xv = sX[(ng * 8 + i) * 64 + k];
                acc[i][0] += xv * w4.x; acc[i][1] += xv * w4.y;
                acc[i][2] += xv * w4.z; acc[i][3] += xv * w4.w;
            }
        }
        float b0 = sb[cg * 4 + 0], b1 = sb[cg * 4 + 1], b2v = sb[cg * 4 + 2], b3v = sb[cg * 4 + 3];
#pragma unroll
        for (int i = 0; i < 8; i++) {
            int li = ng * 8 + i;
            int node = base + li;
            if (node < n) {
                float* pp = d_pool + (size_t)sbt[li] * 128 + cg * 4;
                atomicAdd(pp + 0, lrelu(acc[i][0] + b0, 0.01f));
                atomicAdd(pp + 1, lrelu(acc[i][1] + b1, 0.01f));
                atomicAdd(pp + 2, lrelu(acc[i][2] + b2v, 0.01f));
                atomicAdd(pp + 3, lrelu(acc[i][3] + b3v, 0.01f));
            }
        }
    }
}

__global__ void k_pool_div(int b) {
    int i = blockIdx.x * blockDim.x + threadIdx.x;
    if (i < b * 128) d_pool[i] /= fmaxf(d_cntb[i >> 7], 1.f);
}

// ---------------- sequence branch -------------------------------------------
__global__ void k_conv1(const float* __restrict__ seq, const float* __restrict__ w,
                        const float* __restrict__ bconv,
                        const float* __restrict__ g, const float* __restrict__ be,
                        const float* __restrict__ m, const float* __restrict__ v, int b) {
    __shared__ float sw[64 * 30 * 3];
    for (int i = threadIdx.x; i < 64 * 30 * 3; i += 256) sw[i] = w[i];
    __syncthreads();
    int total = b * 64 * 18;
    for (int idx = blockIdx.x * blockDim.x + threadIdx.x; idx < total; idx += gridDim.x * blockDim.x) {
        int pos = idx % 18, co = (idx / 18) % 64, bb = idx / (18 * 64);
        float acc = bconv[co];
        const float* xb = seq + bb * (CH * SEQL);
        const float* wp = sw + co * 90;
#pragma unroll
        for (int cin = 0; cin < 30; cin++) {
            const float* xp = xb + cin * 20 + pos;
            acc += xp[0] * wp[cin * 3 + 0] + xp[1] * wp[cin * 3 + 1] + xp[2] * wp[cin * 3 + 2];
        }
        float sc = g[co] * rsqrtf(v[co] + 1e-5f);
        float sh = be[co] - m[co] * sc;
        d_s1[idx] = lrelu(acc * sc + sh, 0.01f);
    }
}
__global__ void k_conv2(const float* __restrict__ w, const float* __restrict__ bconv,
                        const float* __restrict__ g, const float* __restrict__ be,
                        const float* __restrict__ m, const float* __restrict__ v, int b) {
    __shared__ float sw[64 * 64 * 3];  // 48KB
    for (int i = threadIdx.x; i < 64 * 64 * 3; i += 256) sw[i] = w[i];
    __syncthreads();
    int total = b * 64 * 16;
    for (int idx = blockIdx.x * blockDim.x + threadIdx.x; idx < total; idx += gridDim.x * blockDim.x) {
        int pos = idx % 16, co = (idx / 16) % 64, bb = idx / (16 * 64);
        float acc = bconv[co];
        const float* xb = d_s1 + bb * (64 * 18);
        const float* wp = sw + co * 192;
#pragma unroll 8
        for (int cin = 0; cin < 64; cin++) {
            const float* xp = xb + cin * 18 + pos;
            acc += xp[0] * wp[cin * 3 + 0] + xp[1] * wp[cin * 3 + 1] + xp[2] * wp[cin * 3 + 2];
        }
        float sc = g[co] * rsqrtf(v[co] + 1e-5f);
        float sh = be[co] - m[co] * sc;
        d_s2[idx] = lrelu(acc * sc + sh, 0.01f);
    }
}

// fc1 as a tiled GEMM: [B,1024] @ [1024,64]  (64 rows per block)
__global__ void k_fc1g(const float* __restrict__ W, const float* __restrict__ bias, int b) {
    __shared__ float sX[64][65];
    __shared__ float sW[64][64];
    int c = threadIdx.x & 63, rg = threadIdx.x >> 6;  // rg in [0,4)
    int rowbase = blockIdx.x * 64;
    float acc[16];
#pragma unroll
    for (int r = 0; r < 16; r++) acc[r] = 0.f;
    for (int kt = 0; kt < 16; kt++) {
        __syncthreads();
        for (int i = threadIdx.x; i < 64 * 64; i += 256) {
            int r = i >> 6, k = i & 63;
            int row = rowbase + r;
            sX[r][k] = (row < b) ? d_s2[row * 1024 + kt * 64 + k] : 0.f;
        }
        for (int i = threadIdx.x; i < 64 * 64; i += 256) {
            int k = i >> 6, cc = i & 63;
            sW[k][cc] = W[(kt * 64 + k) * 64 + cc];
        }
        __syncthreads();
#pragma unroll
        for (int k = 0; k < 64; k++) {
            float w = sW[k][c];
#pragma unroll
            for (int r = 0; r < 16; r++) acc[r] += sX[rg * 16 + r][k] * w;
        }
    }
    float bb = bias[c];
#pragma unroll
    for (int r = 0; r < 16; r++) {
        int row = rowbase + rg * 16 + r;
        if (row < b) d_sfc[row * 64 + c] = acc[r] + bb;
    }
}

// ---------------- fusion + classifier (4 graphs per block) -------------------
__global__ void k_head(const float* __restrict__ fusW, const float* __restrict__ fusb,
                       const float* __restrict__ c1W, const float* __restrict__ c1b,
                       const float* __restrict__ c3W, const float* __restrict__ c3b,
                       float* __restrict__ out, int b) {
    __shared__ float comb[4][192];
    __shared__ float t1[4][128];
    __shared__ float red[4][2];
    int tid = threadIdx.x;
    int b0 = blockIdx.x * 4;
    int nb = min(4, b - b0);
#pragma unroll
    for (int g = 0; g < 4; g++) {
        if (g < nb) {
            comb[g][tid] = d_pool[(b0 + g) * 128 + tid];
            if (tid < 64) comb[g][128 + tid] = d_sfc[(b0 + g) * 64 + tid];
        }
    }
    __syncthreads();
    float a0 = fusb[tid], a1 = a0, a2 = a0, a3 = a0;
    for (int k = 0; k < 192; k++) {
        float w = fusW[k * 128 + tid];
        a0 += comb[0][k] * w; a1 += comb[1][k] * w;
        a2 += comb[2][k] * w; a3 += comb[3][k] * w;
    }
    t1[0][tid] = lrelu(a0, 0.01f); t1[1][tid] = lrelu(a1, 0.01f);
    t1[2][tid] = lrelu(a2, 0.01f); t1[3][tid] = lrelu(a3, 0.01f);
    __syncthreads();
    if (tid < 64) {
        float q0 = c1b[tid], q1 = q0, q2 = q0, q3 = q0;
        for (int k = 0; k < 128; k++) {
            float w = c1W[k * 64 + tid];
            q0 += t1[0][k] * w; q1 += t1[1][k] * w;
            q2 += t1[2][k] * w; q3 += t1[3][k] * w;
        }
        float wc = c3W[tid];
        float v0 = lrelu(q0, 0.01f) * wc;
        float v1 = lrelu(q1, 0.01f) * wc;
        float v2 = lrelu(q2, 0.01f) * wc;
        float v3 = lrelu(q3, 0.01f) * wc;
        v0 = warpSum(v0); v1 = warpSum(v1); v2 = warpSum(v2); v3 = warpSum(v3);
        if ((tid & 31) == 0) {
            int h = tid >> 5;
            red[0][h] = v0; red[1][h] = v1; red[2][h] = v2; red[3][h] = v3;
        }
    }
    __syncthreads();
    if (tid < 4 && tid < nb) out[b0 + tid] = red[tid][0] + red[tid][1] + c3b[0];
}

// ---------------- launch ------------------------------------------------------
extern "C" void kernel_launch(void* const* d_in, const int* in_sizes, int n_in,
                              void* d_out, int out_size) {
    const float* x      = (const float*)d_in[0];
    const int*   ei     = (const int*)d_in[1];
    const int*   batch  = (const int*)d_in[2];
    const float* seq    = (const float*)d_in[3];
    const float* W_gat  = (const float*)d_in[4];
    const float* att_s  = (const float*)d_in[5];
    const float* att_d  = (const float*)d_in[6];
    const float* b_gat  = (const float*)d_in[7];
    const float* W2     = (const float*)d_in[8];
    const float* b2     = (const float*)d_in[9];
    const float* W3     = (const float*)d_in[10];
    const float* b3     = (const float*)d_in[11];
    const float* c1w    = (const float*)d_in[12];
    const float* c1b    = (const float*)d_in[13];
    const float* c2w    = (const float*)d_in[14];
    const float* c2b    = (const float*)d_in[15];
    const float* bn1g   = (const float*)d_in[16];
    const float* bn1b   = (const float*)d_in[17];
    const float* bn1m   = (const float*)d_in[18];
    const float* bn1v   = (const float*)d_in[19];
    const float* bn2g   = (const float*)d_in[20];
    const float* bn2b   = (const float*)d_in[21];
    const float* bn2m   = (const float*)d_in[22];
    const float* bn2v   = (const float*)d_in[23];
    const float* fc1W   = (const float*)d_in[24];
    const float* fc1b   = (const float*)d_in[25];
    const float* fusW   = (const float*)d_in[26];
    const float* fusb   = (const float*)d_in[27];
    const float* cl1W   = (const float*)d_in[28];
    const float* cl1b   = (const float*)d_in[29];
    const float* cl3W   = (const float*)d_in[30];
    const float* cl3b   = (const float*)d_in[31];
    float* out = (float*)d_out;

    int n = in_sizes[0] / 9;
    int E = in_sizes[1] / 2;
    int b = in_sizes[3] / (CH * SEQL);
    if (n > MAXN || E > MAXE || b > BSZ) return;

    // attention precompute + sequence branch + GAT node transform + init
    k_att_pre<<<1, 128>>>(W_gat, att_s, att_d);
    k_conv1<<<512, 256>>>(seq, c1w, c1b, bn1g, bn1b, bn1m, bn1v, b);
    k_conv2<<<512, 256>>>(c2w, c2b, bn2g, bn2b, bn2m, bn2v, b);
    k_fc1g<<<(b + 63) / 64, 256>>>(fc1W, fc1b, b);
    k_gat_node<<<(n + 15) / 16, 128>>>(x, W_gat, n);
    int initN = (n > b * 128 ? n : b * 128);
    k_init<<<(initN + 255) / 256, 256>>>(n, b);
    k_cntb<<<(n + 255) / 256, 256>>>(batch, n);

    // CSR build
    k_count<<<2048, 256>>>(ei, E);
    int NB = (n + 511) / 512;
    k_scan1<<<NB, 512>>>(n);
    k_scan2<<<1, 512>>>(NB);
    k_scan3<<<NB, 512>>>(n, E + n);   // + self loops + cursor + dinv
    k_scatter<<<2048, 256>>>(ei, E);

    // GAT aggregate -> g1 (single pass)
    k_gat_agg<<<(n + 7) / 8, 256>>>(b_gat, n);

    // GCN layer 2: h2 = g1@W2 ; g2 = lrelu(A@h2 + b2)
    k_mm1<<<592, 256>>>(W2, n);
    k_agg64_act<<<(n + 7) / 8, 256>>>(b2, n);

    // GCN layer 3 (linearity): agg = A@g2 (64-dim), then
    // per-node out = lrelu(agg@W3 + b3) accumulated straight into the pool
    k_agg64_plain<<<(n + 7) / 8, 256>>>(n);
    k_mm3pool<<<592, 256>>>(W3, b3, batch, n);
    k_pool_div<<<(b * 128 + 255) / 256, 256>>>(b);

    // fusion + classifier
    k_head<<<(b + 3) / 4, 128>>>(fusW, fusb, cl1W, cl1b, cl3W, cl3b, out, b);
}

// round 17
// speedup vs baseline: 1.5025x; 1.1117x over previous
#include <cuda_runtime.h>
#include <cuda_fp16.h>
#include <math.h>
#include <stdint.h>

// Problem constants (fixed by the dataset)
#define MAXN 100000
#define MAXE 1600000
#define MAXT (MAXN + MAXE)
#define BSZ  1024
#define CH   30
#define SEQL 20

// ---------------- scratch (static device globals; no allocation) -------------
__device__ __half d_h[(size_t)MAXN * 128];   // GAT h (fp16)
__device__ __half d_g1[(size_t)MAXN * 128];  // GAT out g1 (fp16)
__device__ __half d_h2[(size_t)MAXN * 64];   // h2 = g1@W2 (fp16)
__device__ __half d_g2[(size_t)MAXN * 64];   // g2 (fp16)
__device__ __half d_agg[(size_t)MAXN * 64];  // A@g2 (fp16)
__device__ float d_as[MAXN * 4];
__device__ float d_ad[MAXN * 4];
__device__ float d_was[36];  // W_gat @ att_src  [9][4]
__device__ float d_wad[36];  // W_gat @ att_dst  [9][4]
__device__ int   d_deg[MAXN];
__device__ int   d_rowptr[MAXN + 1];
__device__ int   d_cursor[MAXN];
__device__ int   d_col[MAXT];
__device__ int   d_bsums[1024];
__device__ float d_dinv[MAXN];
__device__ float d_pool[BSZ * 128];
__device__ float d_cntb[BSZ];
__device__ float d_s1[BSZ * 64 * 18];
__device__ float d_s2[BSZ * 64 * 16];
__device__ float d_sfc[BSZ * 64];

__device__ __forceinline__ float lrelu(float x, float s) { return x >= 0.f ? x : s * x; }
__device__ __forceinline__ float warpSum(float v) {
#pragma unroll
    for (int o = 16; o > 0; o >>= 1) v += __shfl_xor_sync(0xffffffffu, v, o);
    return v;
}
__device__ __forceinline__ void sth4(__half* p, float4 v) {
    __half2 a = __floats2half2_rn(v.x, v.y);
    __half2 b = __floats2half2_rn(v.z, v.w);
    uint2 u;
    u.x = *reinterpret_cast<unsigned*>(&a);
    u.y = *reinterpret_cast<unsigned*>(&b);
    *(uint2*)p = u;
}

// ---------------- K0: Wa = W_gat @ att (9x4 each, exact algebra) -------------
__global__ void k_att_pre(const float* __restrict__ Wg, const float* __restrict__ asrc,
                          const float* __restrict__ adst) {
    int tid = threadIdx.x;
    if (tid < 72) {
        int idx = tid % 36;
        int f = idx >> 2, hh = idx & 3;
        const float* att = (tid < 36) ? asrc : adst;
        float s = 0.f;
#pragma unroll
        for (int c = 0; c < 32; c++) s += Wg[f * 128 + hh * 32 + c] * att[hh * 32 + c];
        if (tid < 36) d_was[idx] = s; else d_wad[idx] = s;
    }
}

// ---------------- K1: h = x @ W_gat (fp16) ; a_s, a_d via precomputed Wa -----
__global__ void k_gat_node(const float* __restrict__ x, const float* __restrict__ Wg, int n) {
    int lane = threadIdx.x & 31;   // column group: channels 4*lane .. 4*lane+3
    int wid  = threadIdx.x >> 5;   // node-lane 0..3
    float w[9][4];
#pragma unroll
    for (int f = 0; f < 9; f++)
#pragma unroll
        for (int q = 0; q < 4; q++) w[f][q] = Wg[f * 128 + 4 * lane + q];
    __shared__ float sx[16 * 9];
    __shared__ float sWas[36], sWad[36];
    if (threadIdx.x < 36) sWas[threadIdx.x] = d_was[threadIdx.x];
    else if (threadIdx.x < 72) sWad[threadIdx.x - 36] = d_wad[threadIdx.x - 36];
    int base = blockIdx.x * 16;
    int cnt = min(16, n - base);
    if (cnt <= 0) return;
    for (int i = threadIdx.x; i < cnt * 9; i += 128) sx[i] = x[base * 9 + i];
    __syncthreads();
    // attention coefficients: 128 threads -> (li, hh, s/d), 9 FMA each
    {
        int li = threadIdx.x >> 3;
        int hh = (threadIdx.x >> 1) & 3;
        int sd = threadIdx.x & 1;
        if (li < cnt) {
            const float* wa = sd ? sWad : sWas;
            float s = 0.f;
#pragma unroll
            for (int f = 0; f < 9; f++) s += sx[li * 9 + f] * wa[f * 4 + hh];
            if (sd) d_ad[(base + li) * 4 + hh] = s;
            else    d_as[(base + li) * 4 + hh] = s;
        }
    }
    // h rows
#pragma unroll
    for (int t = 0; t < 4; t++) {
        int li = t * 4 + wid;
        int node = base + li;
        if (li >= cnt) break;
        float h[4] = {0.f, 0.f, 0.f, 0.f};
#pragma unroll
        for (int f = 0; f < 9; f++) {
            float xv = sx[li * 9 + f];
#pragma unroll
            for (int q = 0; q < 4; q++) h[q] += xv * w[f][q];
        }
        sth4(d_h + (size_t)node * 128 + 4 * lane, make_float4(h[0], h[1], h[2], h[3]));
    }
}

// ---------------- merged init: pool zero + cntb zero + deg init --------------
__global__ void k_init(int n, int b) {
    int i = blockIdx.x * blockDim.x + threadIdx.x;
    if (i < b * 128) d_pool[i] = 0.f;
    if (i < b) d_cntb[i] = 0.f;
    if (i < n) d_deg[i] = 1;  // self loop
}
__global__ void k_cntb(const int* __restrict__ batch, int n) {
    int i = blockIdx.x * blockDim.x + threadIdx.x;
    if (i < n) atomicAdd(&d_cntb[batch[i]], 1.f);
}

// ---------------- CSR build --------------------------------------------------
__global__ void k_count(const int* __restrict__ ei, int E) {
    for (int e = blockIdx.x * blockDim.x + threadIdx.x; e < E; e += gridDim.x * blockDim.x)
        atomicAdd(&d_deg[ei[E + e]], 1);
}
__global__ void k_scan1(int n) {
    __shared__ int ss[512];
    int idx = blockIdx.x * 512 + threadIdx.x;
    int val = (idx < n) ? d_deg[idx] : 0;
    ss[threadIdx.x] = val;
    __syncthreads();
#pragma unroll
    for (int off = 1; off < 512; off <<= 1) {
        int t = (threadIdx.x >= off) ? ss[threadIdx.x - off] : 0;
        __syncthreads();
        ss[threadIdx.x] += t;
        __syncthreads();
    }
    if (idx < n) d_rowptr[idx] = ss[threadIdx.x] - val;  // exclusive
    if (threadIdx.x == 511) d_bsums[blockIdx.x] = ss[511];
}
__global__ void k_scan2(int nb) {
    __shared__ int ss[512];
    int v = (threadIdx.x < nb) ? d_bsums[threadIdx.x] : 0;
    ss[threadIdx.x] = v;
    __syncthreads();
#pragma unroll
    for (int off = 1; off < 512; off <<= 1) {
        int t = (threadIdx.x >= off) ? ss[threadIdx.x - off] : 0;
        __syncthreads();
        ss[threadIdx.x] += t;
        __syncthreads();
    }
    if (threadIdx.x < nb) d_bsums[threadIdx.x] = ss[threadIdx.x] - v;  // exclusive
}
// scan finalize + self-loop insert + cursor init + dinv (merged)
__global__ void k_scan3(int n, int tot) {
    int idx = blockIdx.x * 512 + threadIdx.x;
    if (idx < n) {
        int rp = d_rowptr[idx] + d_bsums[blockIdx.x];
        d_rowptr[idx] = rp;
        d_col[rp] = idx;          // self loop first
        d_cursor[idx] = rp + 1;
        d_dinv[idx] = rsqrtf((float)d_deg[idx]);
    }
    if (idx == 0) d_rowptr[n] = tot;
}
__global__ void k_scatter(const int* __restrict__ ei, int E) {
    for (int e = blockIdx.x * blockDim.x + threadIdx.x; e < E; e += gridDim.x * blockDim.x) {
        int s = ei[e], d = ei[E + e];
        int pos = atomicAdd(&d_cursor[d], 1);
        d_col[pos] = s;
    }
}

// ---- GAT aggregate: ONE pass, 4 edges in flight per warp-iteration ----------
__global__ void k_gat_agg(const float* __restrict__ bias, int n) {
    int warp = (blockIdx.x * blockDim.x + threadIdx.x) >> 5;
    int lane = threadIdx.x & 31;
    if (warp >= n) return;
    int i = warp;
    int start = d_rowptr[i], end = d_rowptr[i + 1];
    int half = lane >> 4;
    int sub  = lane & 15;
    int head = sub >> 2;
    float4 ad4 = *(const float4*)(d_ad + 4 * i);
    float aad = head < 2 ? (head == 0 ? ad4.x : ad4.y) : (head == 2 ? ad4.z : ad4.w);
    float acc[8] = {0.f, 0.f, 0.f, 0.f, 0.f, 0.f, 0.f, 0.f};
    float ssum = 0.f;
    int jb = start;
    for (; jb + 4 <= end; jb += 4) {
        int j0 = jb + half, j1 = jb + 2 + half;
        int s0 = d_col[j0], s1 = d_col[j1];
        float4 a0 = *(const float4*)(d_as + 4 * s0);
        float4 a1 = *(const float4*)(d_as + 4 * s1);
        uint4 u0 = *(const uint4*)(d_h + (size_t)s0 * 128 + 8 * sub);
        uint4 u1 = *(const uint4*)(d_h + (size_t)s1 * 128 + 8 * sub);
        float av0 = head < 2 ? (head == 0 ? a0.x : a0.y) : (head == 2 ? a0.z : a0.w);
        float av1 = head < 2 ? (head == 0 ? a1.x : a1.y) : (head == 2 ? a1.z : a1.w);
        float w0 = __expf(lrelu(av0 + aad, 0.2f));
        float w1 = __expf(lrelu(av1 + aad, 0.2f));
        ssum += w0 + w1;
        const __half2* hp0 = (const __half2*)&u0;
        const __half2* hp1 = (const __half2*)&u1;
#pragma unroll
        for (int q = 0; q < 4; q++) {
            float2 f0 = __half22float2(hp0[q]);
            float2 f1 = __half22float2(hp1[q]);
            acc[2 * q]     += w0 * f0.x + w1 * f1.x;
            acc[2 * q + 1] += w0 * f0.y + w1 * f1.y;
        }
    }
    for (; jb < end; jb += 2) {
        int j = jb + half;
        if (j < end) {
            int s = d_col[j];
            float4 a = *(const float4*)(d_as + 4 * s);
            float av = head < 2 ? (head == 0 ? a.x : a.y) : (head == 2 ? a.z : a.w);
            float w = __expf(lrelu(av + aad, 0.2f));
            ssum += w;
            uint4 u = *(const uint4*)(d_h + (size_t)s * 128 + 8 * sub);
            const __half2* hp = (const __half2*)&u;
#pragma unroll
            for (int q = 0; q < 4; q++) {
                float2 f = __half22float2(hp[q]);
                acc[2 * q]     += w * f.x;
                acc[2 * q + 1] += w * f.y;
            }
        }
    }
#pragma unroll
    for (int q = 0; q < 8; q++) acc[q] += __shfl_xor_sync(0xffffffffu, acc[q], 16);
    ssum += __shfl_xor_sync(0xffffffffu, ssum, 16);
    if (half == 0) {
        float inv = 1.f / (ssum + 1e-16f);
        const float4* bp = (const float4*)(bias + 8 * sub);
        float4 b0 = bp[0], b1 = bp[1];
        float o0 = lrelu(acc[0] * inv + b0.x, 0.01f);
        float o1 = lrelu(acc[1] * inv + b0.y, 0.01f);
        float o2 = lrelu(acc[2] * inv + b0.z, 0.01f);
        float o3 = lrelu(acc[3] * inv + b0.w, 0.01f);
        float o4 = lrelu(acc[4] * inv + b1.x, 0.01f);
        float o5 = lrelu(acc[5] * inv + b1.y, 0.01f);
        float o6 = lrelu(acc[6] * inv + b1.z, 0.01f);
        float o7 = lrelu(acc[7] * inv + b1.w, 0.01f);
        __half2 p0 = __floats2half2_rn(o0, o1);
        __half2 p1 = __floats2half2_rn(o2, o3);
        __half2 p2 = __floats2half2_rn(o4, o5);
        __half2 p3 = __floats2half2_rn(o6, o7);
        uint4 u;
        u.x = *reinterpret_cast<unsigned*>(&p0);
        u.y = *reinterpret_cast<unsigned*>(&p1);
        u.z = *reinterpret_cast<unsigned*>(&p2);
        u.w = *reinterpret_cast<unsigned*>(&p3);
        *(uint4*)(d_g1 + (size_t)i * 128 + 8 * sub) = u;
    }
}

// ---------------- h2 = g1[N,128] @ W2[128,64]  (register-tiled) --------------
__global__ void k_mm1(const float* __restrict__ W, int n) {
    __shared__ float sW[128 * 64];
    __shared__ float sX[64 * 128];
    const float4* W4 = (const float4*)W;
    float4* sW4 = (float4*)sW;
    for (int i = threadIdx.x; i < 128 * 64 / 4; i += 256) sW4[i] = W4[i];
    int cg = threadIdx.x & 15, ng = threadIdx.x >> 4;
    for (int base = blockIdx.x * 64; base < n; base += gridDim.x * 64) {
        __syncthreads();
        int cnt = min(64, n - base);
        {
            const uint4* src = (const uint4*)(d_g1 + (size_t)base * 128);
            float4* dst = (float4*)sX;
            int tot = cnt * 16;  // uint4 = 8 halves
            for (int i = threadIdx.x; i < tot; i += 256) {
                uint4 u = src[i];
                const __half2* hp = (const __half2*)&u;
                float2 f0 = __half22float2(hp[0]), f1 = __half22float2(hp[1]);
                float2 f2 = __half22float2(hp[2]), f3 = __half22float2(hp[3]);
                dst[2 * i]     = make_float4(f0.x, f0.y, f1.x, f1.y);
                dst[2 * i + 1] = make_float4(f2.x, f2.y, f3.x, f3.y);
            }
        }
        __syncthreads();
        float acc[4][4];
#pragma unroll
        for (int i = 0; i < 4; i++)
#pragma unroll
            for (int q = 0; q < 4; q++) acc[i][q] = 0.f;
        const float4* sWc = (const float4*)sW;
#pragma unroll 4
        for (int k = 0; k < 128; k++) {
            float4 w4 = sWc[k * 16 + cg];
#pragma unroll
            for (int i = 0; i < 4; i++) {
                float xv = sX[(ng * 4 + i) * 128 + k];
                acc[i][0] += xv * w4.x; acc[i][1] += xv * w4.y;
                acc[i][2] += xv * w4.z; acc[i][3] += xv * w4.w;
            }
        }
#pragma unroll
        for (int i = 0; i < 4; i++) {
            int node = base + ng * 4 + i;
            if (node < n)
                sth4(d_h2 + (size_t)node * 64 + cg * 4,
                     make_float4(acc[i][0], acc[i][1], acc[i][2], acc[i][3]));
        }
    }
}

// ------ 64-dim GCN aggregation: 4 edges in flight (fp16 rows) ----------------
__device__ __forceinline__ void agg64_4e(const __half* __restrict__ in, __half* __restrict__ outp,
                                         const float* __restrict__ bias, int n, bool act) {
    int warp = (blockIdx.x * blockDim.x + threadIdx.x) >> 5;
    int lane = threadIdx.x & 31;
    if (warp >= n) return;
    int i = warp;
    int start = d_rowptr[i], end = d_rowptr[i + 1];
    int half = lane >> 4;
    int sub  = lane & 15;
    float dvi = d_dinv[i];
    float a0 = 0.f, a1 = 0.f, a2 = 0.f, a3 = 0.f;
    int jb = start;
    for (; jb + 4 <= end; jb += 4) {
        int j0 = jb + half, j1 = jb + 2 + half;
        int s0 = d_col[j0], s1 = d_col[j1];
        float w0 = d_dinv[s0], w1 = d_dinv[s1];
        uint2 u0 = *(const uint2*)(in + (size_t)s0 * 64 + 4 * sub);
        uint2 u1 = *(const uint2*)(in + (size_t)s1 * 64 + 4 * sub);
        float2 f00 = __half22float2(*reinterpret_cast<const __half2*>(&u0.x));
        float2 f01 = __half22float2(*reinterpret_cast<const __half2*>(&u0.y));
        float2 f10 = __half22float2(*reinterpret_cast<const __half2*>(&u1.x));
        float2 f11 = __half22float2(*reinterpret_cast<const __half2*>(&u1.y));
        a0 += w0 * f00.x + w1 * f10.x;
        a1 += w0 * f00.y + w1 * f10.y;
        a2 += w0 * f01.x + w1 * f11.x;
        a3 += w0 * f01.y + w1 * f11.y;
    }
    for (; jb < end; jb += 2) {
        int j = jb + half;
        if (j < end) {
            int s = d_col[j];
            float w = d_dinv[s];
            uint2 u = *(const uint2*)(in + (size_t)s * 64 + 4 * sub);
            float2 f0 = __half22float2(*reinterpret_cast<const __half2*>(&u.x));
            float2 f1 = __half22float2(*reinterpret_cast<const __half2*>(&u.y));
            a0 += w * f0.x; a1 += w * f0.y; a2 += w * f1.x; a3 += w * f1.y;
        }
    }
    a0 += __shfl_xor_sync(0xffffffffu, a0, 16);
    a1 += __shfl_xor_sync(0xffffffffu, a1, 16);
    a2 += __shfl_xor_sync(0xffffffffu, a2, 16);
    a3 += __shfl_xor_sync(0xffffffffu, a3, 16);
    if (half == 0) {
        a0 *= dvi; a1 *= dvi; a2 *= dvi; a3 *= dvi;
        if (act) {
            float4 b4 = *(const float4*)(bias + 4 * sub);
            a0 = lrelu(a0 + b4.x, 0.01f);
            a1 = lrelu(a1 + b4.y, 0.01f);
            a2 = lrelu(a2 + b4.z, 0.01f);
            a3 = lrelu(a3 + b4.w, 0.01f);
        }
        sth4(outp + (size_t)i * 64 + 4 * sub, make_float4(a0, a1, a2, a3));
    }
}
__global__ void k_agg64_act(const float* __restrict__ bias, int n) {
    agg64_4e(d_h2, d_g2, bias, n, true);     // g2 = lrelu(A@h2 + b2)
}
__global__ void k_agg64_plain(int n) {
    agg64_4e(d_g2, d_agg, nullptr, n, false); // agg = A@g2
}

// ------- layer-3 matmul (64->128) + bias + lrelu + pool (register-tiled) -----
__global__ void k_mm3pool(const float* __restrict__ W, const float* __restrict__ bias,
                          const int* __restrict__ batch, int n) {
    __shared__ float sW[64 * 128];
    __shared__ float sX[64 * 64];
    __shared__ float sb[128];
    __shared__ int sbt[64];
    const float4* W4 = (const float4*)W;
    float4* sW4 = (float4*)sW;
    for (int i = threadIdx.x; i < 64 * 128 / 4; i += 256) sW4[i] = W4[i];
    if (threadIdx.x < 128) sb[threadIdx.x] = bias[threadIdx.x];
    int cg = threadIdx.x & 31, ng = threadIdx.x >> 5;
    for (int base = blockIdx.x * 64; base < n; base += gridDim.x * 64) {
        __syncthreads();
        int cnt = min(64, n - base);
        {
            const uint4* src = (const uint4*)(d_agg + (size_t)base * 64);
            float4* dst = (float4*)sX;
            int tot = cnt * 8;  // uint4 = 8 halves
            for (int i = threadIdx.x; i < tot; i += 256) {
                uint4 u = src[i];
                const __half2* hp = (const __half2*)&u;
                float2 f0 = __half22float2(hp[0]), f1 = __half22float2(hp[1]);
                float2 f2 = __half22float2(hp[2]), f3 = __half22float2(hp[3]);
                dst[2 * i]     = make_float4(f0.x, f0.y, f1.x, f1.y);
                dst[2 * i + 1] = make_float4(f2.x, f2.y, f3.x, f3.y);
            }
        }
        if (threadIdx.x < 64 && threadIdx.x < cnt) sbt[threadIdx.x] = batch[base + threadIdx.x];
        __syncthreads();
        float acc[8][4];
#pragma unroll
        for (int i = 0; i < 8; i++)
#pragma unroll
            for (int q = 0; q < 4; q++) acc[i][q] = 0.f;
        const float4* sWc = (const float4*)sW;
#pragma unroll 4
        for (int k = 0; k < 64; k++) {
            float4 w4 = sWc[k * 32 + cg];
#pragma unroll
            for (int i = 0; i < 8; i++) {
                float xv = sX[(ng * 8 + i) * 64 + k];
                acc[i][0] += xv * w4.x; acc[i][1] += xv * w4.y;
                acc[i][2] += xv * w4.z; acc[i][3] += xv * w4.w;
            }
        }
        float b0 = sb[cg * 4 + 0], b1 = sb[cg * 4 + 1], b2v = sb[cg * 4 + 2], b3v = sb[cg * 4 + 3];
#pragma unroll
        for (int i = 0; i < 8; i++) {
            int li = ng * 8 + i;
            int node = base + li;
            if (node < n) {
                float* pp = d_pool + (size_t)sbt[li] * 128 + cg * 4;
                atomicAdd(pp + 0, lrelu(acc[i][0] + b0, 0.01f));
                atomicAdd(pp + 1, lrelu(acc[i][1] + b1, 0.01f));
                atomicAdd(pp + 2, lrelu(acc[i][2] + b2v, 0.01f));
                atomicAdd(pp + 3, lrelu(acc[i][3] + b3v, 0.01f));
            }
        }
    }
}

__global__ void k_pool_div(int b) {
    int i = blockIdx.x * blockDim.x + threadIdx.x;
    if (i < b * 128) d_pool[i] /= fmaxf(d_cntb[i >> 7], 1.f);
}

// ---------------- sequence branch -------------------------------------------
__global__ void k_conv1(const float* __restrict__ seq, const float* __restrict__ w,
                        const float* __restrict__ bconv,
                        const float* __restrict__ g, const float* __restrict__ be,
                        const float* __restrict__ m, const float* __restrict__ v, int b) {
    __shared__ float sw[64 * 30 * 3];
    for (int i = threadIdx.x; i < 64 * 30 * 3; i += 256) sw[i] = w[i];
    __syncthreads();
    int total = b * 64 * 18;
    for (int idx = blockIdx.x * blockDim.x + threadIdx.x; idx < total; idx += gridDim.x * blockDim.x) {
        int pos = idx % 18, co = (idx / 18) % 64, bb = idx / (18 * 64);
        float acc = bconv[co];
        const float* xb = seq + bb * (CH * SEQL);
        const float* wp = sw + co * 90;
#pragma unroll
        for (int cin = 0; cin < 30; cin++) {
            const float* xp = xb + cin * 20 + pos;
            acc += xp[0] * wp[cin * 3 + 0] + xp[1] * wp[cin * 3 + 1] + xp[2] * wp[cin * 3 + 2];
        }
        float sc = g[co] * rsqrtf(v[co] + 1e-5f);
        float sh = be[co] - m[co] * sc;
        d_s1[idx] = lrelu(acc * sc + sh, 0.01f);
    }
}
__global__ void k_conv2(const float* __restrict__ w, const float* __restrict__ bconv,
                        const float* __restrict__ g, const float* __restrict__ be,
                        const float* __restrict__ m, const float* __restrict__ v, int b) {
    __shared__ float sw[64 * 64 * 3];  // 48KB
    for (int i = threadIdx.x; i < 64 * 64 * 3; i += 256) sw[i] = w[i];
    __syncthreads();
    int total = b * 64 * 16;
    for (int idx = blockIdx.x * blockDim.x + threadIdx.x; idx < total; idx += gridDim.x * blockDim.x) {
        int pos = idx % 16, co = (idx / 16) % 64, bb = idx / (16 * 64);
        float acc = bconv[co];
        const float* xb = d_s1 + bb * (64 * 18);
        const float* wp = sw + co * 192;
#pragma unroll 8
        for (int cin = 0; cin < 64; cin++) {
            const float* xp = xb + cin * 18 + pos;
            acc += xp[0] * wp[cin * 3 + 0] + xp[1] * wp[cin * 3 + 1] + xp[2] * wp[cin * 3 + 2];
        }
        float sc = g[co] * rsqrtf(v[co] + 1e-5f);
        float sh = be[co] - m[co] * sc;
        d_s2[idx] = lrelu(acc * sc + sh, 0.01f);
    }
}

// ---- fc1: [B,1024]@[1024,64] — 8 rows/block, full-chip occupancy ------------
// block 256: c = tid&63 (output col), rg = tid>>6 (row pair: rows 2rg, 2rg+1)
// X rows in smem (broadcast reads within warp); W streamed from L2, coalesced.
__global__ void k_fc1g(const float* __restrict__ W, const float* __restrict__ bias, int b) {
    __shared__ float sX[8 * 1024];  // 32 KB
    int rowbase = blockIdx.x * 8;
    int nrows = min(8, b - rowbase);
    if (nrows <= 0) return;
    {
        const float4* src = (const float4*)(d_s2 + (size_t)rowbase * 1024);
        float4* dst = (float4*)sX;
        int tot = nrows * 256;
        for (int i = threadIdx.x; i < tot; i += 256) dst[i] = src[i];
    }
    __syncthreads();
    int c = threadIdx.x & 63;
    int rg = threadIdx.x >> 6;  // 0..3
    const float* x0 = sX + (2 * rg) * 1024;
    const float* x1 = sX + (2 * rg + 1) * 1024;
    float acc0 = 0.f, acc1 = 0.f;
#pragma unroll 4
    for (int k = 0; k < 1024; k += 4) {
        float w0 = W[(k + 0) * 64 + c];
        float w1 = W[(k + 1) * 64 + c];
        float w2 = W[(k + 2) * 64 + c];
        float w3 = W[(k + 3) * 64 + c];
        acc0 += x0[k] * w0 + x0[k + 1] * w1 + x0[k + 2] * w2 + x0[k + 3] * w3;
        acc1 += x1[k] * w0 + x1[k + 1] * w1 + x1[k + 2] * w2 + x1[k + 3] * w3;
    }
    float bb = bias[c];
    int r0 = rowbase + 2 * rg, r1 = r0 + 1;
    if (2 * rg < nrows)     d_sfc[r0 * 64 + c] = acc0 + bb;
    if (2 * rg + 1 < nrows) d_sfc[r1 * 64 + c] = acc1 + bb;
}

// ---------------- fusion + classifier (4 graphs per block) -------------------
__global__ void k_head(const float* __restrict__ fusW, const float* __restrict__ fusb,
                       const float* __restrict__ c1W, const float* __restrict__ c1b,
                       const float* __restrict__ c3W, const float* __restrict__ c3b,
                       float* __restrict__ out, int b) {
    __shared__ float comb[4][192];
    __shared__ float t1[4][128];
    __shared__ float red[4][2];
    int tid = threadIdx.x;
    int b0 = blockIdx.x * 4;
    int nb = min(4, b - b0);
#pragma unroll
    for (int g = 0; g < 4; g++) {
        if (g < nb) {
            comb[g][tid] = d_pool[(b0 + g) * 128 + tid];
            if (tid < 64) comb[g][128 + tid] = d_sfc[(b0 + g) * 64 + tid];
        }
    }
    __syncthreads();
    float a0 = fusb[tid], a1 = a0, a2 = a0, a3 = a0;
    for (int k = 0; k < 192; k++) {
        float w = fusW[k * 128 + tid];
        a0 += comb[0][k] * w; a1 += comb[1][k] * w;
        a2 += comb[2][k] * w; a3 += comb[3][k] * w;
    }
    t1[0][tid] = lrelu(a0, 0.01f); t1[1][tid] = lrelu(a1, 0.01f);
    t1[2][tid] = lrelu(a2, 0.01f); t1[3][tid] = lrelu(a3, 0.01f);
    __syncthreads();
    if (tid < 64) {
        float q0 = c1b[tid], q1 = q0, q2 = q0, q3 = q0;
        for (int k = 0; k < 128; k++) {
            float w = c1W[k * 64 + tid];
            q0 += t1[0][k] * w; q1 += t1[1][k] * w;
            q2 += t1[2][k] * w; q3 += t1[3][k] * w;
        }
        float wc = c3W[tid];
        float v0 = lrelu(q0, 0.01f) * wc;
        float v1 = lrelu(q1, 0.01f) * wc;
        float v2 = lrelu(q2, 0.01f) * wc;
        float v3 = lrelu(q3, 0.01f) * wc;
        v0 = warpSum(v0); v1 = warpSum(v1); v2 = warpSum(v2); v3 = warpSum(v3);
        if ((tid & 31) == 0) {
            int h = tid >> 5;
            red[0][h] = v0; red[1][h] = v1; red[2][h] = v2; red[3][h] = v3;
        }
    }
    __syncthreads();
    if (tid < 4 && tid < nb) out[b0 + tid] = red[tid][0] + red[tid][1] + c3b[0];
}

// ---------------- launch ------------------------------------------------------
extern "C" void kernel_launch(void* const* d_in, const int* in_sizes, int n_in,
                              void* d_out, int out_size) {
    const float* x      = (const float*)d_in[0];
    const int*   ei     = (const int*)d_in[1];
    const int*   batch  = (const int*)d_in[2];
    const float* seq    = (const float*)d_in[3];
    const float* W_gat  = (const float*)d_in[4];
    const float* att_s  = (const float*)d_in[5];
    const float* att_d  = (const float*)d_in[6];
    const float* b_gat  = (const float*)d_in[7];
    const float* W2     = (const float*)d_in[8];
    const float* b2     = (const float*)d_in[9];
    const float* W3     = (const float*)d_in[10];
    const float* b3     = (const float*)d_in[11];
    const float* c1w    = (const float*)d_in[12];
    const float* c1b    = (const float*)d_in[13];
    const float* c2w    = (const float*)d_in[14];
    const float* c2b    = (const float*)d_in[15];
    const float* bn1g   = (const float*)d_in[16];
    const float* bn1b   = (const float*)d_in[17];
    const float* bn1m   = (const float*)d_in[18];
    const float* bn1v   = (const float*)d_in[19];
    const float* bn2g   = (const float*)d_in[20];
    const float* bn2b   = (const float*)d_in[21];
    const float* bn2m   = (const float*)d_in[22];
    const float* bn2v   = (const float*)d_in[23];
    const float* fc1W   = (const float*)d_in[24];
    const float* fc1b   = (const float*)d_in[25];
    const float* fusW   = (const float*)d_in[26];
    const float* fusb   = (const float*)d_in[27];
    const float* cl1W   = (const float*)d_in[28];
    const float* cl1b   = (const float*)d_in[29];
    const float* cl3W   = (const float*)d_in[30];
    const float* cl3b   = (const float*)d_in[31];
    float* out = (float*)d_out;

    int n = in_sizes[0] / 9;
    int E = in_sizes[1] / 2;
    int b = in_sizes[3] / (CH * SEQL);
    if (n > MAXN || E > MAXE || b > BSZ) return;

    // attention precompute + sequence branch + GAT node transform + init
    k_att_pre<<<1, 128>>>(W_gat, att_s, att_d);
    k_conv1<<<512, 256>>>(seq, c1w, c1b, bn1g, bn1b, bn1m, bn1v, b);
    k_conv2<<<512, 256>>>(c2w, c2b, bn2g, bn2b, bn2m, bn2v, b);
    k_fc1g<<<(b + 7) / 8, 256>>>(fc1W, fc1b, b);
    k_gat_node<<<(n + 15) / 16, 128>>>(x, W_gat, n);
    int initN = (n > b * 128 ? n : b * 128);
    k_init<<<(initN + 255) / 256, 256>>>(n, b);
    k_cntb<<<(n + 255) / 256, 256>>>(batch, n);

    // CSR build
    k_count<<<2048, 256>>>(ei, E);
    int NB = (n + 511) / 512;
    k_scan1<<<NB, 512>>>(n);
    k_scan2<<<1, 512>>>(NB);
    k_scan3<<<NB, 512>>>(n, E + n);   // + self loops + cursor + dinv
    k_scatter<<<2048, 256>>>(ei, E);

    // GAT aggregate -> g1 (single pass)
    k_gat_agg<<<(n + 7) / 8, 256>>>(b_gat, n);

    // GCN layer 2: h2 = g1@W2 ; g2 = lrelu(A@h2 + b2)
    k_mm1<<<592, 256>>>(W2, n);
    k_agg64_act<<<(n + 7) / 8, 256>>>(b2, n);

    // GCN layer 3 (linearity): agg = A@g2 (64-dim), then
    // per-node out = lrelu(agg@W3 + b3) accumulated straight into the pool
    k_agg64_plain<<<(n + 7) / 8, 256>>>(n);
    k_mm3pool<<<592, 256>>>(W3, b3, batch, n);
    k_pool_div<<<(b * 128 + 255) / 256, 256>>>(b);

    // fusion + classifier
    k_head<<<(b + 3) / 4, 128>>>(fusW, fusb, cl1W, cl1b, cl3W, cl3b, out, b);
}